// round 1
// baseline (speedup 1.0000x reference)
#include <cuda_runtime.h>

// Problem constants (fixed by setup_inputs)
#define BQ   4      // batch
#define NLYR 2      // layers (only last used)
#define NP   100    // passages
#define NTOK 60     // tokens per passage
#define NTOT 6000   // NP*NTOK
#define DD   768    // hidden
#define NTAB 10     // tables

// ---------------- scratch (device globals; no allocation allowed) ----------
__device__ float g_G[DD * 2 * DD];                      // [768][1536] = [G1 | G2]
__device__ float g_cp[BQ * DD];                          // c_p per batch
__device__ float g_Wbig[BQ * 2 * DD * DD];               // [b][1536][768] = [M_t ; N]
__device__ float g_bias[BQ * 2 * DD];                    // [b][1536]     = [c_t ; u]
__device__ float g_Y[(size_t)BQ * NTOT * 2 * DD];        // [b][6000][1536] = [ts | part1]
__device__ float g_tmax[BQ * NTAB * NTOK * DD];          // [b][10][60][768]
__device__ float g_p2[BQ * NTAB * NTOK * DD];            // Wf1_a @ tmax

// ---------------- generic strided fp32 GEMM: C[m,n] = sum_k A[m,k]*B[n,k] ---
// A: A[bz*a_bs + m*a_rs + k]   (k contiguous)
// B: B[bz*b_bs + n*b_ns + k*b_ks]
// C: C[bz*c_bs + m*c_ld + n] (+ bias[bz*bias_bs + n])
// Requires K % 16 == 0, N % 128 == 0. M may be ragged.
__global__ __launch_bounds__(256)
void gemm_k(const float* __restrict__ A, long a_rs, long a_bs,
            const float* __restrict__ Bm, long b_ns, long b_ks, long b_bs,
            const float* __restrict__ bias, long bias_bs,
            float* __restrict__ C, long c_ld, long c_bs,
            int M, int N, int K)
{
    const int BM = 128, BN = 128, BK = 16;
    __shared__ float As[BK][BM + 4];
    __shared__ float Bs[BK][BN + 4];

    int bz = blockIdx.z;
    const float* Ab = A  + (long)bz * a_bs;
    const float* Bb = Bm + (long)bz * b_bs;
    float*       Cb = C  + (long)bz * c_bs;

    int m0  = blockIdx.y * BM;
    int n0  = blockIdx.x * BN;
    int tid = threadIdx.x;
    int tx  = tid & 15;   // n dir, 16 * 8 = 128
    int ty  = tid >> 4;   // m dir, 16 * 8 = 128

    float acc[8][8];
    #pragma unroll
    for (int i = 0; i < 8; i++)
        #pragma unroll
        for (int j = 0; j < 8; j++) acc[i][j] = 0.f;

    for (int k0 = 0; k0 < K; k0 += BK) {
        #pragma unroll
        for (int i = 0; i < 8; i++) {
            int e = tid + i * 256;
            int m = e >> 4;
            int k = e & 15;
            float v = 0.f;
            if (m0 + m < M) v = Ab[(long)(m0 + m) * a_rs + (k0 + k)];
            As[k][m] = v;
        }
        #pragma unroll
        for (int i = 0; i < 8; i++) {
            int e = tid + i * 256;
            int n = e >> 4;
            int k = e & 15;
            Bs[k][n] = Bb[(long)(n0 + n) * b_ns + (long)(k0 + k) * b_ks];
        }
        __syncthreads();

        #pragma unroll
        for (int kk = 0; kk < BK; kk++) {
            float a[8], bb[8];
            #pragma unroll
            for (int i = 0; i < 8; i++) a[i]  = As[kk][ty * 8 + i];
            #pragma unroll
            for (int j = 0; j < 8; j++) bb[j] = Bs[kk][tx * 8 + j];
            #pragma unroll
            for (int i = 0; i < 8; i++)
                #pragma unroll
                for (int j = 0; j < 8; j++) acc[i][j] += a[i] * bb[j];
        }
        __syncthreads();
    }

    #pragma unroll
    for (int i = 0; i < 8; i++) {
        int m = m0 + ty * 8 + i;
        if (m < M) {
            #pragma unroll
            for (int j = 0; j < 8; j++) {
                int n = n0 + tx * 8 + j;
                float v = acc[i][j];
                if (bias) v += bias[(long)bz * bias_bs + n];
                Cb[(long)m * c_ld + n] = v;
            }
        }
    }
}

// ---------------- prep kernels ---------------------------------------------
// c_p[b][d] = bp[d] + sum_k Wp[d, k]   * A[b,k]   (first D block)
// c_t[b][d] = bt[d] + sum_k Wt[d, k]   * A[b,k]
__global__ void prep1_k(const float* __restrict__ ans, const float* __restrict__ Wp,
                        const float* __restrict__ bp, const float* __restrict__ Wt,
                        const float* __restrict__ bt)
{
    int b = blockIdx.y;
    int d = blockIdx.x * blockDim.x + threadIdx.x;
    const float* Av = ans + (long)(b * NLYR + (NLYR - 1)) * DD;
    float sp = bp[d], st = bt[d];
    const float* wpr = Wp + (long)d * 3 * DD;
    const float* wtr = Wt + (long)d * 3 * DD;
    for (int k = 0; k < DD; k++) {
        float a = Av[k];
        sp += wpr[k] * a;
        st += wtr[k] * a;
    }
    g_cp[b * DD + d] = sp;
    g_bias[b * 2 * DD + d] = st;   // c_t half of the big bias
}

// u[b][d] = bf1[d] + sum_k Wf1[d, k] * c_p[b][k]   (Wf1_p block)
__global__ void prep_u_k(const float* __restrict__ Wf1, const float* __restrict__ bf1)
{
    int b = blockIdx.y;
    int d = blockIdx.x * blockDim.x + threadIdx.x;
    const float* cp = g_cp + b * DD;
    const float* wr = Wf1 + (long)d * 2 * DD;
    float s = bf1[d];
    for (int k = 0; k < DD; k++) s += wr[k] * cp[k];
    g_bias[b * 2 * DD + DD + d] = s;   // u half
}

// Wbig[b][j][k]: j<768 -> M_t[j,k] = Wt[j, D+k] + Wt[j, 2D+k]*A[b,k]
//               j>=768 -> N[d,k]   = G1[d,k]   + G2[d,k]    *A[b,k]
__global__ void wbig_k(const float* __restrict__ ans, const float* __restrict__ Wt)
{
    long idx = (long)blockIdx.x * blockDim.x + threadIdx.x;
    if (idx >= (long)BQ * 2 * DD * DD) return;
    int k = (int)(idx % DD);
    long r = idx / DD;
    int j = (int)(r % (2 * DD));
    int b = (int)(r / (2 * DD));
    float a = ans[(long)(b * NLYR + (NLYR - 1)) * DD + k];
    float v;
    if (j < DD) {
        const float* wr = Wt + (long)j * 3 * DD;
        v = wr[DD + k] + wr[2 * DD + k] * a;
    } else {
        int d = j - DD;
        const float* gr = g_G + (long)d * 2 * DD;
        v = gr[k] + gr[DD + k] * a;
    }
    g_Wbig[idx] = v;
}

// ---------------- group max over passages by table id ----------------------
__global__ void tmax_k(const int* __restrict__ tids)
{
    int b   = blockIdx.x / NTOK;
    int tok = blockIdx.x % NTOK;
    int d   = threadIdx.x;              // 768 threads
    __shared__ int ids[NP];
    if (threadIdx.x < NP) ids[threadIdx.x] = tids[b * NP + threadIdx.x];
    float m[NTAB];
    #pragma unroll
    for (int t = 0; t < NTAB; t++) m[t] = -3.0e38f;
    __syncthreads();
    const float* Yb = g_Y + (long)b * NTOT * 2 * DD;
    for (int p = 0; p < NP; p++) {
        float v = Yb[(long)(p * NTOK + tok) * 2 * DD + d];   // ts half
        int id = ids[p];
        #pragma unroll
        for (int t = 0; t < NTAB; t++)
            if (id == t) m[t] = fmaxf(m[t], v);
    }
    #pragma unroll
    for (int t = 0; t < NTAB; t++)
        g_tmax[(((long)b * NTAB + t) * NTOK + tok) * DD + d] = m[t];
}

// ---------------- final: relu, dot Wf2, masked token sum -------------------
__global__ void final_k(const float* __restrict__ masks, const int* __restrict__ tids,
                        const float* __restrict__ Wf2, const float* __restrict__ bf2,
                        float* __restrict__ out)
{
    int b = blockIdx.x / NP, p = blockIdx.x % NP;
    int tbl = tids[b * NP + p];
    __shared__ float w2[DD];
    __shared__ float ms[NTOK];
    __shared__ float red[256];
    for (int i = threadIdx.x; i < DD; i += blockDim.x) w2[i] = Wf2[i];
    if (threadIdx.x < NTOK) ms[threadIdx.x] = masks[(b * NP + p) * NTOK + threadIdx.x];
    __syncthreads();

    const float* p1 = g_Y + ((long)b * NTOT + (long)p * NTOK) * 2 * DD + DD; // part1 half
    const float* p2 = g_p2 + ((long)b * NTAB + tbl) * NTOK * DD;
    float bv = bf2[0];
    float acc = 0.f;
    for (int idx = threadIdx.x; idx < NTOK * DD; idx += blockDim.x) {
        int tok = idx / DD, d = idx % DD;
        float v = p1[(long)tok * 2 * DD + d] + p2[tok * DD + d];
        float s = ms[tok] * w2[d] * fmaxf(v, 0.f);
        if (d == 0) s += bv * ms[tok];
        acc += s;
    }
    red[threadIdx.x] = acc;
    __syncthreads();
    for (int s = 128; s > 0; s >>= 1) {
        if (threadIdx.x < s) red[threadIdx.x] += red[threadIdx.x + s];
        __syncthreads();
    }
    if (threadIdx.x == 0) out[b * NP + p] = red[0];
}

// ---------------- launcher --------------------------------------------------
extern "C" void kernel_launch(void* const* d_in, const int* in_sizes, int n_in,
                              void* d_out, int out_size)
{
    const float* ans   = (const float*)d_in[0];   // (4,2,1,768)
    const float* qps   = (const float*)d_in[1];   // (4,2,6000,768)
    const float* masks = (const float*)d_in[2];   // (4,100,60)
    const int*   tids  = (const int*)  d_in[3];   // (4,100)
    const float* Wp    = (const float*)d_in[4];   // (768,2304)
    const float* bp    = (const float*)d_in[5];
    const float* Wt    = (const float*)d_in[6];
    const float* bt    = (const float*)d_in[7];
    const float* Wf1   = (const float*)d_in[8];   // (768,1536)
    const float* bf1   = (const float*)d_in[9];
    const float* Wf2   = (const float*)d_in[10];  // (1,768)
    const float* bf2   = (const float*)d_in[11];  // (1,)
    float* out = (float*)d_out;

    void *pG, *pWbig, *pBias, *pY, *pTmax, *pP2;
    cudaGetSymbolAddress(&pG,    g_G);
    cudaGetSymbolAddress(&pWbig, g_Wbig);
    cudaGetSymbolAddress(&pBias, g_bias);
    cudaGetSymbolAddress(&pY,    g_Y);
    cudaGetSymbolAddress(&pTmax, g_tmax);
    cudaGetSymbolAddress(&pP2,   g_p2);

    // 1) G = Wf1_p @ [Wp_Q | Wp_AQ]  : M=768, N=1536, K=768
    //    A[m,k] = Wf1[m*1536 + k];  B[n,k] = Wp[k*2304 + 768 + n]
    gemm_k<<<dim3(1536 / 128, 768 / 128, 1), 256>>>(
        Wf1, 2 * DD, 0,
        Wp + DD, 1, 3 * DD, 0,
        (const float*)nullptr, 0,
        (float*)pG, 2 * DD, 0,
        DD, 2 * DD, DD);

    // 2) per-batch c_p, c_t
    prep1_k<<<dim3(3, BQ), 256>>>(ans, Wp, bp, Wt, bt);
    // 3) u = bf1 + Wf1_p @ c_p
    prep_u_k<<<dim3(3, BQ), 256>>>(Wf1, bf1);
    // 4) Wbig fill (needs G)
    {
        long tot = (long)BQ * 2 * DD * DD;
        wbig_k<<<(unsigned)((tot + 255) / 256), 256>>>(ans, Wt);
    }

    // 5) main GEMM: Y[b,t,:] = Q[b,t,:] @ Wbig[b]^T + bias[b]
    //    M=6000, N=1536, K=768 per batch
    gemm_k<<<dim3(1536 / 128, (NTOT + 127) / 128, BQ), 256>>>(
        qps + (long)(NLYR - 1) * NTOT * DD, DD, (long)NLYR * NTOT * DD,
        (const float*)pWbig, DD, 1, (long)2 * DD * DD,
        (const float*)pBias, 2 * DD,
        (float*)pY, 2 * DD, (long)NTOT * 2 * DD,
        NTOT, 2 * DD, DD);

    // 6) group max of ts over passages by table
    tmax_k<<<BQ * NTOK, DD>>>(tids);

    // 7) part2 = tmax @ Wf1_a^T : M=600, N=768, K=768 per batch
    gemm_k<<<dim3(768 / 128, (NTAB * NTOK + 127) / 128, BQ), 256>>>(
        (const float*)pTmax, DD, (long)NTAB * NTOK * DD,
        Wf1 + DD, 2 * DD, 1, 0,
        (const float*)nullptr, 0,
        (float*)pP2, DD, (long)NTAB * NTOK * DD,
        NTAB * NTOK, DD, DD);

    // 8) final masked score reduction -> out (4,100)
    final_k<<<BQ * NP, 256>>>(masks, tids, Wf2, bf2, out);
}

// round 3
// speedup vs baseline: 1.6864x; 1.6864x over previous
#include <cuda_runtime.h>
#include <cuda_bf16.h>
#include <cstdint>

// Problem constants (fixed by setup_inputs)
#define BQ   4
#define NLYR 2
#define NP   100
#define NTOK 60
#define NTOT 6000
#define DD   768
#define NTAB 10

#define MT   47          // m tiles of 128 (6016 >= 6000)
#define NT   6           // n image tiles of 256 (1536); CTA n-tile is 128
#define NT2  12          // CTA n tiles of 128
#define NSLAB 12         // k slabs of 64
#define ATILE_B 16384    // 128x64 bf16 (one image tile)
#define BTILE_B 32768    // 256x64 bf16 (one image tile)
#define HTILE_B 16384    // 128-row half of a B image tile
#define STAGE_B (4 * 16384)   // Ahi,Alo,Bhi,Blo halves: 64KB per stage

// ---------------- scratch ---------------------------------------------------
__device__ float g_G[DD * 2 * DD];
__device__ float g_cp[BQ * DD];
__device__ float g_bias[BQ * 2 * DD];
__device__ float g_Y[(size_t)BQ * NTOT * 2 * DD];
__device__ float g_tmax[BQ * NTAB * NTOK * DD];
__device__ float g_p2[BQ * NTAB * NTOK * DD];
// pre-swizzled bf16 tile images
__device__ unsigned char g_Qhi[(size_t)BQ * MT * NSLAB * ATILE_B];
__device__ unsigned char g_Qlo[(size_t)BQ * MT * NSLAB * ATILE_B];
__device__ unsigned char g_Whi[(size_t)BQ * NT * NSLAB * BTILE_B];
__device__ unsigned char g_Wlo[(size_t)BQ * NT * NSLAB * BTILE_B];

// ---------------- PTX helpers ----------------------------------------------
__device__ __forceinline__ uint32_t smem_u32(const void* p) {
    uint32_t a;
    asm("{ .reg .u64 t; cvta.to.shared.u64 t, %1; cvt.u32.u64 %0, t; }" : "=r"(a) : "l"(p));
    return a;
}
__device__ __forceinline__ void cpasync16(uint32_t dst, const void* src) {
    asm volatile("cp.async.cg.shared.global [%0], [%1], 16;" :: "r"(dst), "l"(src));
}
__device__ __forceinline__ void cp_commit() {
    asm volatile("cp.async.commit_group;" ::: "memory");
}
__device__ __forceinline__ void ldm_x4(uint32_t* r, uint32_t addr) {
    asm volatile("ldmatrix.sync.aligned.m8n8.x4.shared.b16 {%0,%1,%2,%3}, [%4];"
                 : "=r"(r[0]), "=r"(r[1]), "=r"(r[2]), "=r"(r[3]) : "r"(addr));
}
__device__ __forceinline__ void mma16816(float* d, const uint32_t* a,
                                         uint32_t b0, uint32_t b1) {
    asm volatile(
        "mma.sync.aligned.m16n8k16.row.col.f32.bf16.bf16.f32 "
        "{%0,%1,%2,%3}, {%4,%5,%6,%7}, {%8,%9}, {%0,%1,%2,%3};"
        : "+f"(d[0]), "+f"(d[1]), "+f"(d[2]), "+f"(d[3])
        : "r"(a[0]), "r"(a[1]), "r"(a[2]), "r"(a[3]), "r"(b0), "r"(b1));
}
// swizzled ldmatrix lane address within a 128-row x 64-col bf16 SW128 tile
__device__ __forceinline__ uint32_t ldm_addr(uint32_t tilebase, int row0, int k0, int lane) {
    int row = row0 + (lane & 15);
    int kc  = k0 + ((lane >> 4) << 3);
    uint32_t off = (uint32_t)(row * 128 + kc * 2);
    off ^= (off >> 3) & 0x70;
    return tilebase + off;
}

// ---------------- SIMT GEMM (small ops) -------------------------------------
__global__ __launch_bounds__(256)
void gemm_k(const float* __restrict__ A, long a_rs, long a_bs,
            const float* __restrict__ Bm, long b_ns, long b_ks, long b_bs,
            const float* __restrict__ bias, long bias_bs,
            float* __restrict__ C, long c_ld, long c_bs,
            int M, int N, int K)
{
    const int BM = 128, BN = 128, BK = 16;
    __shared__ float As[BK][BM + 4];
    __shared__ float Bs[BK][BN + 4];
    int bz = blockIdx.z;
    const float* Ab = A  + (long)bz * a_bs;
    const float* Bb = Bm + (long)bz * b_bs;
    float*       Cb = C  + (long)bz * c_bs;
    int m0 = blockIdx.y * BM, n0 = blockIdx.x * BN;
    int tid = threadIdx.x, tx = tid & 15, ty = tid >> 4;
    float acc[8][8];
    #pragma unroll
    for (int i = 0; i < 8; i++)
        #pragma unroll
        for (int j = 0; j < 8; j++) acc[i][j] = 0.f;
    for (int k0 = 0; k0 < K; k0 += BK) {
        #pragma unroll
        for (int i = 0; i < 8; i++) {
            int e = tid + i * 256, m = e >> 4, k = e & 15;
            float v = 0.f;
            if (m0 + m < M) v = Ab[(long)(m0 + m) * a_rs + (k0 + k)];
            As[k][m] = v;
        }
        #pragma unroll
        for (int i = 0; i < 8; i++) {
            int e = tid + i * 256, n = e >> 4, k = e & 15;
            Bs[k][n] = Bb[(long)(n0 + n) * b_ns + (long)(k0 + k) * b_ks];
        }
        __syncthreads();
        #pragma unroll
        for (int kk = 0; kk < BK; kk++) {
            float a[8], bb[8];
            #pragma unroll
            for (int i = 0; i < 8; i++) a[i]  = As[kk][ty * 8 + i];
            #pragma unroll
            for (int j = 0; j < 8; j++) bb[j] = Bs[kk][tx * 8 + j];
            #pragma unroll
            for (int i = 0; i < 8; i++)
                #pragma unroll
                for (int j = 0; j < 8; j++) acc[i][j] += a[i] * bb[j];
        }
        __syncthreads();
    }
    #pragma unroll
    for (int i = 0; i < 8; i++) {
        int m = m0 + ty * 8 + i;
        if (m < M) {
            #pragma unroll
            for (int j = 0; j < 8; j++) {
                int n = n0 + tx * 8 + j;
                float v = acc[i][j];
                if (bias) v += bias[(long)bz * bias_bs + n];
                Cb[(long)m * c_ld + n] = v;
            }
        }
    }
}

// ---------------- prep kernels ----------------------------------------------
__global__ void prep1_k(const float* __restrict__ ans, const float* __restrict__ Wp,
                        const float* __restrict__ bp, const float* __restrict__ Wt,
                        const float* __restrict__ bt)
{
    int b = blockIdx.y;
    int d = blockIdx.x * blockDim.x + threadIdx.x;
    const float* Av = ans + (long)(b * NLYR + (NLYR - 1)) * DD;
    float sp = bp[d], st = bt[d];
    const float* wpr = Wp + (long)d * 3 * DD;
    const float* wtr = Wt + (long)d * 3 * DD;
    for (int k = 0; k < DD; k++) {
        float a = Av[k];
        sp += wpr[k] * a;
        st += wtr[k] * a;
    }
    g_cp[b * DD + d] = sp;
    g_bias[b * 2 * DD + d] = st;
}

__global__ void prep_u_k(const float* __restrict__ Wf1, const float* __restrict__ bf1)
{
    int b = blockIdx.y;
    int d = blockIdx.x * blockDim.x + threadIdx.x;
    const float* cp = g_cp + b * DD;
    const float* wr = Wf1 + (long)d * 2 * DD;
    float s = bf1[d];
    for (int k = 0; k < DD; k++) s += wr[k] * cp[k];
    g_bias[b * 2 * DD + DD + d] = s;
}

// ---------------- bf16 split helpers ----------------------------------------
__device__ __forceinline__ void split8(const float* v, uint4& hi, uint4& lo) {
    unsigned short h[8], l[8];
    #pragma unroll
    for (int i = 0; i < 8; i++) {
        __nv_bfloat16 bh = __float2bfloat16_rn(v[i]);
        float r = v[i] - __bfloat162float(bh);
        __nv_bfloat16 bl = __float2bfloat16_rn(r);
        h[i] = __bfloat16_as_ushort(bh);
        l[i] = __bfloat16_as_ushort(bl);
    }
    hi.x = h[0] | ((uint32_t)h[1] << 16); hi.y = h[2] | ((uint32_t)h[3] << 16);
    hi.z = h[4] | ((uint32_t)h[5] << 16); hi.w = h[6] | ((uint32_t)h[7] << 16);
    lo.x = l[0] | ((uint32_t)l[1] << 16); lo.y = l[2] | ((uint32_t)l[3] << 16);
    lo.z = l[4] | ((uint32_t)l[5] << 16); lo.w = l[6] | ((uint32_t)l[7] << 16);
}

// Q -> swizzled bf16 hi/lo tile images. thread = (b, mt, r, c8)
__global__ __launch_bounds__(256) void qsplit_k(const float* __restrict__ qps)
{
    long idx = (long)blockIdx.x * 256 + threadIdx.x;
    int c8 = (int)(idx % 96);
    long t  = idx / 96;
    int r  = (int)(t % 128);
    t /= 128;
    int mt = (int)(t % MT);
    int b  = (int)(t / MT);
    if (b >= BQ) return;
    int m = mt * 128 + r;
    int k0 = c8 * 8;
    float v[8];
    if (m < NTOT) {
        const float* src = qps + ((long)(b * NLYR + 1) * NTOT + m) * DD + k0;
        float4 a = ((const float4*)src)[0];
        float4 c = ((const float4*)src)[1];
        v[0]=a.x; v[1]=a.y; v[2]=a.z; v[3]=a.w; v[4]=c.x; v[5]=c.y; v[6]=c.z; v[7]=c.w;
    } else {
        #pragma unroll
        for (int i = 0; i < 8; i++) v[i] = 0.f;
    }
    uint4 hi, lo;
    split8(v, hi, lo);
    int kslab = k0 >> 6, cin = k0 & 63;
    uint32_t off = (uint32_t)(r * 128 + cin * 2);
    off ^= ((off >> 3) & 0x70);
    long base = (((long)(b * MT + mt) * NSLAB + kslab) << 14) + off;
    *(uint4*)(g_Qhi + base) = hi;
    *(uint4*)(g_Qlo + base) = lo;
}

// Wbig -> swizzled bf16 hi/lo tile images. thread = (b, nt, r, c8)
__global__ __launch_bounds__(256) void wsplit_k(const float* __restrict__ ans,
                                                const float* __restrict__ Wt)
{
    long idx = (long)blockIdx.x * 256 + threadIdx.x;
    int c8 = (int)(idx % 96);
    long t  = idx / 96;
    int r  = (int)(t % 256);
    t /= 256;
    int nt = (int)(t % NT);
    int b  = (int)(t / NT);
    if (b >= BQ) return;
    int j = nt * 256 + r;
    int k0 = c8 * 8;
    const float* Av = ans + (long)(b * NLYR + 1) * DD + k0;
    float a[8], w1[8], w2[8];
    {
        float4 x = ((const float4*)Av)[0], y = ((const float4*)Av)[1];
        a[0]=x.x; a[1]=x.y; a[2]=x.z; a[3]=x.w; a[4]=y.x; a[5]=y.y; a[6]=y.z; a[7]=y.w;
    }
    if (j < DD) {
        const float* wr = Wt + (long)j * 3 * DD;
        float4 x = *(const float4*)(wr + DD + k0),     y = *(const float4*)(wr + DD + k0 + 4);
        float4 u = *(const float4*)(wr + 2 * DD + k0), w = *(const float4*)(wr + 2 * DD + k0 + 4);
        w1[0]=x.x; w1[1]=x.y; w1[2]=x.z; w1[3]=x.w; w1[4]=y.x; w1[5]=y.y; w1[6]=y.z; w1[7]=y.w;
        w2[0]=u.x; w2[1]=u.y; w2[2]=u.z; w2[3]=u.w; w2[4]=w.x; w2[5]=w.y; w2[6]=w.z; w2[7]=w.w;
    } else {
        int d = j - DD;
        const float* gr = g_G + (long)d * 2 * DD;
        float4 x = *(const float4*)(gr + k0),      y = *(const float4*)(gr + k0 + 4);
        float4 u = *(const float4*)(gr + DD + k0), w = *(const float4*)(gr + DD + k0 + 4);
        w1[0]=x.x; w1[1]=x.y; w1[2]=x.z; w1[3]=x.w; w1[4]=y.x; w1[5]=y.y; w1[6]=y.z; w1[7]=y.w;
        w2[0]=u.x; w2[1]=u.y; w2[2]=u.z; w2[3]=u.w; w2[4]=w.x; w2[5]=w.y; w2[6]=w.z; w2[7]=w.w;
    }
    float v[8];
    #pragma unroll
    for (int i = 0; i < 8; i++) v[i] = w1[i] + w2[i] * a[i];
    uint4 hi, lo;
    split8(v, hi, lo);
    int kslab = k0 >> 6, cin = k0 & 63;
    uint32_t off = (uint32_t)(r * 128 + cin * 2);
    off ^= ((off >> 3) & 0x70);
    long base = (((long)(b * NT + nt) * NSLAB + kslab) << 15) + off;
    *(uint4*)(g_Whi + base) = hi;
    *(uint4*)(g_Wlo + base) = lo;
}

// ---------------- HMMA main GEMM (mma.sync bf16x3) ---------------------------
// stage layout: [Ahi 16K][Alo 16K][Bhi(128 rows) 16K][Blo 16K]
__device__ __forceinline__ void copy_slab(uint32_t sb,
    const unsigned char* qh, const unsigned char* ql,
    const unsigned char* wh, const unsigned char* wl, int tid)
{
    int o = tid * 16;   // 256 threads * 16B = 4KB per sweep
    #pragma unroll
    for (int t = 0; t < 4; t++) cpasync16(sb + o + t * 4096,             qh + o + t * 4096);
    #pragma unroll
    for (int t = 0; t < 4; t++) cpasync16(sb + 16384 + o + t * 4096,     ql + o + t * 4096);
    #pragma unroll
    for (int t = 0; t < 4; t++) cpasync16(sb + 32768 + o + t * 4096,     wh + o + t * 4096);
    #pragma unroll
    for (int t = 0; t < 4; t++) cpasync16(sb + 49152 + o + t * 4096,     wl + o + t * 4096);
    cp_commit();
}

__global__ __launch_bounds__(256)
void tgemm_k(const float* __restrict__ bias, float* __restrict__ Y)
{
    extern __shared__ __align__(1024) unsigned char dsm[];
    uint32_t dbase = smem_u32(dsm);

    int tid  = threadIdx.x;
    int lane = tid & 31;
    int w    = tid >> 5;
    int mw   = w >> 2;        // 0..1 : 64-row block
    int nw   = w & 3;         // 0..3 : 32-col block
    int b    = blockIdx.z;
    int nt2  = blockIdx.x;    // 0..11 (128-col tiles)
    int mt   = blockIdx.y;    // 0..46

    const unsigned char* qh = g_Qhi + (((long)(b * MT + mt) * NSLAB) << 14);
    const unsigned char* ql = g_Qlo + (((long)(b * MT + mt) * NSLAB) << 14);
    long wbase = (((long)(b * NT + (nt2 >> 1)) * NSLAB) << 15) + (long)(nt2 & 1) * HTILE_B;
    const unsigned char* wh = g_Whi + wbase;
    const unsigned char* wl = g_Wlo + wbase;

    float acc[4][4][4];
    #pragma unroll
    for (int i = 0; i < 4; i++)
        #pragma unroll
        for (int j = 0; j < 4; j++)
            #pragma unroll
            for (int k = 0; k < 4; k++) acc[i][j][k] = 0.f;

    // prologue: slabs 0,1  (B slab stride is BTILE_B within the image)
    copy_slab(dbase,           qh,           ql,           wh,           wl,           tid);
    copy_slab(dbase + STAGE_B, qh + ATILE_B, ql + ATILE_B, wh + BTILE_B, wl + BTILE_B, tid);

    for (int i = 0; i < NSLAB; i++) {
        uint32_t sb = dbase + (uint32_t)(i & 1) * STAGE_B;
        if (i < NSLAB - 1) asm volatile("cp.async.wait_group 1;" ::: "memory");
        else               asm volatile("cp.async.wait_group 0;" ::: "memory");
        __syncthreads();

        uint32_t ah_t = sb,        al_t = sb + 16384;
        uint32_t bh_t = sb + 32768, bl_t = sb + 49152;

        #pragma unroll
        for (int kk = 0; kk < 64; kk += 16) {
            uint32_t Bh[8], Bl[8];
            #pragma unroll
            for (int g = 0; g < 2; g++) {
                ldm_x4(&Bh[g * 4], ldm_addr(bh_t, nw * 32 + g * 16, kk, lane));
                ldm_x4(&Bl[g * 4], ldm_addr(bl_t, nw * 32 + g * 16, kk, lane));
            }
            #pragma unroll
            for (int mf = 0; mf < 4; mf++) {
                uint32_t Ah[4], Al[4];
                ldm_x4(Ah, ldm_addr(ah_t, mw * 64 + mf * 16, kk, lane));
                ldm_x4(Al, ldm_addr(al_t, mw * 64 + mf * 16, kk, lane));
                #pragma unroll
                for (int nf = 0; nf < 4; nf++) {
                    int g = nf >> 1, q = nf & 1;
                    uint32_t b0h = Bh[g * 4 + q],     b1h = Bh[g * 4 + 2 + q];
                    uint32_t b0l = Bl[g * 4 + q],     b1l = Bl[g * 4 + 2 + q];
                    mma16816(acc[mf][nf], Ah, b0h, b1h);   // hi*hi
                    mma16816(acc[mf][nf], Ah, b0l, b1l);   // hi*lo
                    mma16816(acc[mf][nf], Al, b0h, b1h);   // lo*hi
                }
            }
        }
        __syncthreads();
        if (i + 2 < NSLAB) {
            int sl = i + 2;
            copy_slab(sb, qh + (long)sl * ATILE_B, ql + (long)sl * ATILE_B,
                          wh + (long)sl * BTILE_B, wl + (long)sl * BTILE_B, tid);
        }
    }

    // ---- epilogue: direct STG with fused bias ----
    long yb = (long)b * NTOT * (2 * DD);
    #pragma unroll
    for (int nf = 0; nf < 4; nf++) {
        int col = nt2 * 128 + nw * 32 + nf * 8 + (lane & 3) * 2;
        float bv0 = bias[b * 2 * DD + col];
        float bv1 = bias[b * 2 * DD + col + 1];
        #pragma unroll
        for (int mf = 0; mf < 4; mf++) {
            int r0 = mt * 128 + mw * 64 + mf * 16 + (lane >> 2);
            int r1 = r0 + 8;
            float* acp = acc[mf][nf];
            if (r0 < NTOT) {
                float2 v = make_float2(acp[0] + bv0, acp[1] + bv1);
                *(float2*)(Y + yb + (long)r0 * (2 * DD) + col) = v;
            }
            if (r1 < NTOT) {
                float2 v = make_float2(acp[2] + bv0, acp[3] + bv1);
                *(float2*)(Y + yb + (long)r1 * (2 * DD) + col) = v;
            }
        }
    }
}

// ---------------- group max over passages by table id -----------------------
__global__ void tmax_k(const int* __restrict__ tids)
{
    int b   = blockIdx.x / NTOK;
    int tok = blockIdx.x % NTOK;
    int d   = threadIdx.x;
    __shared__ int ids[NP];
    if (threadIdx.x < NP) ids[threadIdx.x] = tids[b * NP + threadIdx.x];
    float m[NTAB];
    #pragma unroll
    for (int t = 0; t < NTAB; t++) m[t] = -3.0e38f;
    __syncthreads();
    const float* Yb = g_Y + (long)b * NTOT * 2 * DD;
    for (int p = 0; p < NP; p++) {
        float v = Yb[(long)(p * NTOK + tok) * 2 * DD + d];
        int id = ids[p];
        #pragma unroll
        for (int t = 0; t < NTAB; t++)
            if (id == t) m[t] = fmaxf(m[t], v);
    }
    #pragma unroll
    for (int t = 0; t < NTAB; t++)
        g_tmax[(((long)b * NTAB + t) * NTOK + tok) * DD + d] = m[t];
}

// ---------------- final -----------------------------------------------------
__global__ void final_k(const float* __restrict__ masks, const int* __restrict__ tids,
                        const float* __restrict__ Wf2, const float* __restrict__ bf2,
                        float* __restrict__ out)
{
    int b = blockIdx.x / NP, p = blockIdx.x % NP;
    int tbl = tids[b * NP + p];
    __shared__ float w2[DD];
    __shared__ float ms[NTOK];
    __shared__ float red[256];
    for (int i = threadIdx.x; i < DD; i += blockDim.x) w2[i] = Wf2[i];
    if (threadIdx.x < NTOK) ms[threadIdx.x] = masks[(b * NP + p) * NTOK + threadIdx.x];
    __syncthreads();

    const float* p1 = g_Y + ((long)b * NTOT + (long)p * NTOK) * 2 * DD + DD;
    const float* p2 = g_p2 + ((long)b * NTAB + tbl) * NTOK * DD;
    float bv = bf2[0];
    float acc = 0.f;
    for (int idx = threadIdx.x; idx < NTOK * DD; idx += blockDim.x) {
        int tok = idx / DD, d = idx % DD;
        float v = p1[(long)tok * 2 * DD + d] + p2[tok * DD + d];
        float s = ms[tok] * w2[d] * fmaxf(v, 0.f);
        if (d == 0) s += bv * ms[tok];
        acc += s;
    }
    red[threadIdx.x] = acc;
    __syncthreads();
    for (int s = 128; s > 0; s >>= 1) {
        if (threadIdx.x < s) red[threadIdx.x] += red[threadIdx.x + s];
        __syncthreads();
    }
    if (threadIdx.x == 0) out[b * NP + p] = red[0];
}

// ---------------- launcher --------------------------------------------------
extern "C" void kernel_launch(void* const* d_in, const int* in_sizes, int n_in,
                              void* d_out, int out_size)
{
    const float* ans   = (const float*)d_in[0];
    const float* qps   = (const float*)d_in[1];
    const float* masks = (const float*)d_in[2];
    const int*   tids  = (const int*)  d_in[3];
    const float* Wp    = (const float*)d_in[4];
    const float* bp    = (const float*)d_in[5];
    const float* Wt    = (const float*)d_in[6];
    const float* bt    = (const float*)d_in[7];
    const float* Wf1   = (const float*)d_in[8];
    const float* bf1   = (const float*)d_in[9];
    const float* Wf2   = (const float*)d_in[10];
    const float* bf2   = (const float*)d_in[11];
    float* out = (float*)d_out;

    void *pG, *pBias, *pY, *pTmax, *pP2;
    cudaGetSymbolAddress(&pG,    g_G);
    cudaGetSymbolAddress(&pBias, g_bias);
    cudaGetSymbolAddress(&pY,    g_Y);
    cudaGetSymbolAddress(&pTmax, g_tmax);
    cudaGetSymbolAddress(&pP2,   g_p2);

    // 1) G = Wf1_p @ [Wp_Q | Wp_AQ]
    gemm_k<<<dim3(1536 / 128, 768 / 128, 1), 256>>>(
        Wf1, 2 * DD, 0,
        Wp + DD, 1, 3 * DD, 0,
        (const float*)nullptr, 0,
        (float*)pG, 2 * DD, 0,
        DD, 2 * DD, DD);

    // 2) per-batch c_p, c_t ; 3) u
    prep1_k<<<dim3(3, BQ), 256>>>(ans, Wp, bp, Wt, bt);
    prep_u_k<<<dim3(3, BQ), 256>>>(Wf1, bf1);

    // 4) prepack Q and Wbig as swizzled bf16 hi/lo tile images
    {
        long tq = (long)BQ * MT * 128 * 96;
        qsplit_k<<<(unsigned)((tq + 255) / 256), 256>>>(qps);
        long tw = (long)BQ * NT * 256 * 96;
        wsplit_k<<<(unsigned)((tw + 255) / 256), 256>>>(ans, Wt);
    }

    // 5) main GEMM via mma.sync (bf16x3 split)
    {
        int dyn = 2 * STAGE_B;   // 128KB
        cudaFuncSetAttribute(tgemm_k, cudaFuncAttributeMaxDynamicSharedMemorySize, dyn);
        tgemm_k<<<dim3(NT2, MT, BQ), 256, dyn>>>((const float*)pBias, (float*)pY);
    }

    // 6) table group-max
    tmax_k<<<BQ * NTOK, DD>>>(tids);

    // 7) part2 = tmax @ Wf1_a^T
    gemm_k<<<dim3(768 / 128, (NTAB * NTOK + 127) / 128, BQ), 256>>>(
        (const float*)pTmax, DD, (long)NTAB * NTOK * DD,
        Wf1 + DD, 2 * DD, 1, 0,
        (const float*)nullptr, 0,
        (float*)pP2, DD, (long)NTAB * NTOK * DD,
        NTAB * NTOK, DD, DD);

    // 8) final masked reduction
    final_k<<<BQ * NP, 256>>>(masks, tids, Wf2, bf2, out);
}

// round 4
// speedup vs baseline: 1.7420x; 1.0330x over previous
#include <cuda_runtime.h>
#include <cuda_bf16.h>
#include <cstdint>

// Problem constants (fixed by setup_inputs)
#define BQ   4
#define NLYR 2
#define NP   100
#define NTOK 60
#define NTOT 6000
#define DD   768
#define NTAB 10

#define MT   47          // m tiles of 128 (6016 >= 6000)
#define NT   6           // n tiles of 256 (1536)
#define NS32 24          // k slabs of 32
#define AT32 8192        // 128 rows x 32 k bf16 = 8KB
#define BT32 16384       // 256 rows x 32 k bf16 = 16KB
#define STG32 49152      // stage: Ahi+Alo+Bhi+Blo = 8+8+16+16 KB

// ---------------- scratch ---------------------------------------------------
__device__ float g_G[DD * 2 * DD];
__device__ float g_cp[BQ * DD];
__device__ float g_bias[BQ * 2 * DD];
__device__ float g_Y[(size_t)BQ * NTOT * 2 * DD];
__device__ float g_tmax[BQ * NTAB * NTOK * DD];
__device__ float g_p2[BQ * NTAB * NTOK * DD];
// pre-swizzled bf16 tile images (SW64, 64B rows, 32-k slabs)
__device__ unsigned char g_Qhi[(size_t)BQ * MT * NS32 * AT32];
__device__ unsigned char g_Qlo[(size_t)BQ * MT * NS32 * AT32];
__device__ unsigned char g_Whi[(size_t)BQ * NT * NS32 * BT32];
__device__ unsigned char g_Wlo[(size_t)BQ * NT * NS32 * BT32];

// ---------------- PTX helpers ----------------------------------------------
__device__ __forceinline__ uint32_t smem_u32(const void* p) {
    uint32_t a;
    asm("{ .reg .u64 t; cvta.to.shared.u64 t, %1; cvt.u32.u64 %0, t; }" : "=r"(a) : "l"(p));
    return a;
}
__device__ __forceinline__ void cpasync16(uint32_t dst, const void* src) {
    asm volatile("cp.async.cg.shared.global [%0], [%1], 16;" :: "r"(dst), "l"(src));
}
__device__ __forceinline__ void cp_commit() {
    asm volatile("cp.async.commit_group;" ::: "memory");
}
__device__ __forceinline__ void ldm_x4(uint32_t* r, uint32_t addr) {
    asm volatile("ldmatrix.sync.aligned.m8n8.x4.shared.b16 {%0,%1,%2,%3}, [%4];"
                 : "=r"(r[0]), "=r"(r[1]), "=r"(r[2]), "=r"(r[3]) : "r"(addr));
}
__device__ __forceinline__ void mma16816(float* d, const uint32_t* a,
                                         uint32_t b0, uint32_t b1) {
    asm volatile(
        "mma.sync.aligned.m16n8k16.row.col.f32.bf16.bf16.f32 "
        "{%0,%1,%2,%3}, {%4,%5,%6,%7}, {%8,%9}, {%0,%1,%2,%3};"
        : "+f"(d[0]), "+f"(d[1]), "+f"(d[2]), "+f"(d[3])
        : "r"(a[0]), "r"(a[1]), "r"(a[2]), "r"(a[3]), "r"(b0), "r"(b1));
}
// SW64-swizzled ldmatrix lane address within a (rows x 32k) bf16 tile, 64B rows
__device__ __forceinline__ uint32_t ldm_addr64(uint32_t tilebase, int row0, int k0, int lane) {
    int row = row0 + (lane & 15);
    int kc  = k0 + ((lane >> 4) << 3);
    uint32_t off = (uint32_t)(row * 64 + kc * 2);
    off ^= (off >> 3) & 0x30;
    return tilebase + off;
}
__device__ __forceinline__ uint32_t swz64(uint32_t off) {
    return off ^ ((off >> 3) & 0x30);
}

// ---------------- SIMT GEMM (small ops) -------------------------------------
__global__ __launch_bounds__(256)
void gemm_k(const float* __restrict__ A, long a_rs, long a_bs,
            const float* __restrict__ Bm, long b_ns, long b_ks, long b_bs,
            const float* __restrict__ bias, long bias_bs,
            float* __restrict__ C, long c_ld, long c_bs,
            int M, int N, int K)
{
    const int BM = 128, BN = 128, BK = 16;
    __shared__ float As[BK][BM + 4];
    __shared__ float Bs[BK][BN + 4];
    int bz = blockIdx.z;
    const float* Ab = A  + (long)bz * a_bs;
    const float* Bb = Bm + (long)bz * b_bs;
    float*       Cb = C  + (long)bz * c_bs;
    int m0 = blockIdx.y * BM, n0 = blockIdx.x * BN;
    int tid = threadIdx.x, tx = tid & 15, ty = tid >> 4;
    float acc[8][8];
    #pragma unroll
    for (int i = 0; i < 8; i++)
        #pragma unroll
        for (int j = 0; j < 8; j++) acc[i][j] = 0.f;
    for (int k0 = 0; k0 < K; k0 += BK) {
        #pragma unroll
        for (int i = 0; i < 8; i++) {
            int e = tid + i * 256, m = e >> 4, k = e & 15;
            float v = 0.f;
            if (m0 + m < M) v = Ab[(long)(m0 + m) * a_rs + (k0 + k)];
            As[k][m] = v;
        }
        #pragma unroll
        for (int i = 0; i < 8; i++) {
            int e = tid + i * 256, n = e >> 4, k = e & 15;
            Bs[k][n] = Bb[(long)(n0 + n) * b_ns + (long)(k0 + k) * b_ks];
        }
        __syncthreads();
        #pragma unroll
        for (int kk = 0; kk < BK; kk++) {
            float a[8], bb[8];
            #pragma unroll
            for (int i = 0; i < 8; i++) a[i]  = As[kk][ty * 8 + i];
            #pragma unroll
            for (int j = 0; j < 8; j++) bb[j] = Bs[kk][tx * 8 + j];
            #pragma unroll
            for (int i = 0; i < 8; i++)
                #pragma unroll
                for (int j = 0; j < 8; j++) acc[i][j] += a[i] * bb[j];
        }
        __syncthreads();
    }
    #pragma unroll
    for (int i = 0; i < 8; i++) {
        int m = m0 + ty * 8 + i;
        if (m < M) {
            #pragma unroll
            for (int j = 0; j < 8; j++) {
                int n = n0 + tx * 8 + j;
                float v = acc[i][j];
                if (bias) v += bias[(long)bz * bias_bs + n];
                Cb[(long)m * c_ld + n] = v;
            }
        }
    }
}

// ---------------- prep kernels ----------------------------------------------
__global__ void prep1_k(const float* __restrict__ ans, const float* __restrict__ Wp,
                        const float* __restrict__ bp, const float* __restrict__ Wt,
                        const float* __restrict__ bt)
{
    int b = blockIdx.y;
    int d = blockIdx.x * blockDim.x + threadIdx.x;
    const float* Av = ans + (long)(b * NLYR + (NLYR - 1)) * DD;
    float sp = bp[d], st = bt[d];
    const float* wpr = Wp + (long)d * 3 * DD;
    const float* wtr = Wt + (long)d * 3 * DD;
    for (int k = 0; k < DD; k++) {
        float a = Av[k];
        sp += wpr[k] * a;
        st += wtr[k] * a;
    }
    g_cp[b * DD + d] = sp;
    g_bias[b * 2 * DD + d] = st;
}

__global__ void prep_u_k(const float* __restrict__ Wf1, const float* __restrict__ bf1)
{
    int b = blockIdx.y;
    int d = blockIdx.x * blockDim.x + threadIdx.x;
    const float* cp = g_cp + b * DD;
    const float* wr = Wf1 + (long)d * 2 * DD;
    float s = bf1[d];
    for (int k = 0; k < DD; k++) s += wr[k] * cp[k];
    g_bias[b * 2 * DD + DD + d] = s;
}

// ---------------- bf16 split helpers ----------------------------------------
__device__ __forceinline__ void split8(const float* v, uint4& hi, uint4& lo) {
    unsigned short h[8], l[8];
    #pragma unroll
    for (int i = 0; i < 8; i++) {
        __nv_bfloat16 bh = __float2bfloat16_rn(v[i]);
        float r = v[i] - __bfloat162float(bh);
        __nv_bfloat16 bl = __float2bfloat16_rn(r);
        h[i] = __bfloat16_as_ushort(bh);
        l[i] = __bfloat16_as_ushort(bl);
    }
    hi.x = h[0] | ((uint32_t)h[1] << 16); hi.y = h[2] | ((uint32_t)h[3] << 16);
    hi.z = h[4] | ((uint32_t)h[5] << 16); hi.w = h[6] | ((uint32_t)h[7] << 16);
    lo.x = l[0] | ((uint32_t)l[1] << 16); lo.y = l[2] | ((uint32_t)l[3] << 16);
    lo.z = l[4] | ((uint32_t)l[5] << 16); lo.w = l[6] | ((uint32_t)l[7] << 16);
}

// Q -> SW64 bf16 hi/lo tile images. thread = (b, mt, r, c8)
__global__ __launch_bounds__(256) void qsplit_k(const float* __restrict__ qps)
{
    long idx = (long)blockIdx.x * 256 + threadIdx.x;
    int c8 = (int)(idx % 96);
    long t  = idx / 96;
    int r  = (int)(t % 128);
    t /= 128;
    int mt = (int)(t % MT);
    int b  = (int)(t / MT);
    if (b >= BQ) return;
    int m = mt * 128 + r;
    int k0 = c8 * 8;
    float v[8];
    if (m < NTOT) {
        const float* src = qps + ((long)(b * NLYR + 1) * NTOT + m) * DD + k0;
        float4 a = ((const float4*)src)[0];
        float4 c = ((const float4*)src)[1];
        v[0]=a.x; v[1]=a.y; v[2]=a.z; v[3]=a.w; v[4]=c.x; v[5]=c.y; v[6]=c.z; v[7]=c.w;
    } else {
        #pragma unroll
        for (int i = 0; i < 8; i++) v[i] = 0.f;
    }
    uint4 hi, lo;
    split8(v, hi, lo);
    int slab = k0 >> 5, kin = k0 & 31;
    uint32_t off = swz64((uint32_t)(r * 64 + kin * 2));
    long base = ((long)(b * MT + mt) * NS32 + slab) * AT32 + off;
    *(uint4*)(g_Qhi + base) = hi;
    *(uint4*)(g_Qlo + base) = lo;
}

// Wbig -> SW64 bf16 hi/lo tile images. thread = (b, nt, r, c8)
__global__ __launch_bounds__(256) void wsplit_k(const float* __restrict__ ans,
                                                const float* __restrict__ Wt)
{
    long idx = (long)blockIdx.x * 256 + threadIdx.x;
    int c8 = (int)(idx % 96);
    long t  = idx / 96;
    int r  = (int)(t % 256);
    t /= 256;
    int nt = (int)(t % NT);
    int b  = (int)(t / NT);
    if (b >= BQ) return;
    int j = nt * 256 + r;
    int k0 = c8 * 8;
    const float* Av = ans + (long)(b * NLYR + 1) * DD + k0;
    float a[8], w1[8], w2[8];
    {
        float4 x = ((const float4*)Av)[0], y = ((const float4*)Av)[1];
        a[0]=x.x; a[1]=x.y; a[2]=x.z; a[3]=x.w; a[4]=y.x; a[5]=y.y; a[6]=y.z; a[7]=y.w;
    }
    if (j < DD) {
        const float* wr = Wt + (long)j * 3 * DD;
        float4 x = *(const float4*)(wr + DD + k0),     y = *(const float4*)(wr + DD + k0 + 4);
        float4 u = *(const float4*)(wr + 2 * DD + k0), w = *(const float4*)(wr + 2 * DD + k0 + 4);
        w1[0]=x.x; w1[1]=x.y; w1[2]=x.z; w1[3]=x.w; w1[4]=y.x; w1[5]=y.y; w1[6]=y.z; w1[7]=y.w;
        w2[0]=u.x; w2[1]=u.y; w2[2]=u.z; w2[3]=u.w; w2[4]=w.x; w2[5]=w.y; w2[6]=w.z; w2[7]=w.w;
    } else {
        int d = j - DD;
        const float* gr = g_G + (long)d * 2 * DD;
        float4 x = *(const float4*)(gr + k0),      y = *(const float4*)(gr + k0 + 4);
        float4 u = *(const float4*)(gr + DD + k0), w = *(const float4*)(gr + DD + k0 + 4);
        w1[0]=x.x; w1[1]=x.y; w1[2]=x.z; w1[3]=x.w; w1[4]=y.x; w1[5]=y.y; w1[6]=y.z; w1[7]=y.w;
        w2[0]=u.x; w2[1]=u.y; w2[2]=u.z; w2[3]=u.w; w2[4]=w.x; w2[5]=w.y; w2[6]=w.z; w2[7]=w.w;
    }
    float v[8];
    #pragma unroll
    for (int i = 0; i < 8; i++) v[i] = w1[i] + w2[i] * a[i];
    uint4 hi, lo;
    split8(v, hi, lo);
    int slab = k0 >> 5, kin = k0 & 31;
    uint32_t off = swz64((uint32_t)(r * 64 + kin * 2));
    long base = ((long)(b * NT + nt) * NS32 + slab) * BT32 + off;
    *(uint4*)(g_Whi + base) = hi;
    *(uint4*)(g_Wlo + base) = lo;
}

// ---------------- HMMA main GEMM --------------------------------------------
// stage layout: [Ahi 8K][Alo 8K][Bhi 16K][Blo 16K] = 48KB
__device__ __forceinline__ void copy_slab32(uint32_t sb,
    const unsigned char* qh, const unsigned char* ql,
    const unsigned char* wh, const unsigned char* wl, int tid)
{
    int o = tid * 16;   // 256 threads * 16B = 4KB per sweep
    #pragma unroll
    for (int t = 0; t < 2; t++) cpasync16(sb + o + t * 4096,              qh + o + t * 4096);
    #pragma unroll
    for (int t = 0; t < 2; t++) cpasync16(sb + 8192 + o + t * 4096,       ql + o + t * 4096);
    #pragma unroll
    for (int t = 0; t < 4; t++) cpasync16(sb + 16384 + o + t * 4096,      wh + o + t * 4096);
    #pragma unroll
    for (int t = 0; t < 4; t++) cpasync16(sb + 32768 + o + t * 4096,      wl + o + t * 4096);
    cp_commit();
}

__global__ __launch_bounds__(256, 1)
void tgemm_k(const float* __restrict__ bias, float* __restrict__ Y)
{
    extern __shared__ __align__(1024) unsigned char dsm[];
    uint32_t dbase = smem_u32(dsm);

    int tid  = threadIdx.x;
    int lane = tid & 31;
    int w    = tid >> 5;
    int mw   = w >> 2;        // 0..1 : 64-row block
    int nw   = w & 3;         // 0..3 : 64-col block
    int b    = blockIdx.z;
    int nt   = blockIdx.x;    // 0..5 (256-col tiles)
    int mt   = blockIdx.y;    // 0..46

    const unsigned char* qh = g_Qhi + ((long)(b * MT + mt) * NS32) * AT32;
    const unsigned char* ql = g_Qlo + ((long)(b * MT + mt) * NS32) * AT32;
    const unsigned char* wh = g_Whi + ((long)(b * NT + nt) * NS32) * BT32;
    const unsigned char* wl = g_Wlo + ((long)(b * NT + nt) * NS32) * BT32;

    float acc[4][8][4];
    #pragma unroll
    for (int i = 0; i < 4; i++)
        #pragma unroll
        for (int j = 0; j < 8; j++)
            #pragma unroll
            for (int k = 0; k < 4; k++) acc[i][j][k] = 0.f;

    // prologue: stages 0,1,2
    copy_slab32(dbase,             qh,            ql,            wh,            wl,            tid);
    copy_slab32(dbase + STG32,     qh + AT32,     ql + AT32,     wh + BT32,     wl + BT32,     tid);
    copy_slab32(dbase + 2 * STG32, qh + 2 * AT32, ql + 2 * AT32, wh + 2 * BT32, wl + 2 * BT32, tid);

    for (int i = 0; i < NS32; i++) {
        asm volatile("cp.async.wait_group 2;" ::: "memory");
        __syncthreads();
        // prefetch slab i+3 into stage (i+3)&3 == (i-1)&3 (consumed at iter i-1)
        if (i + 3 < NS32) {
            int sl = i + 3;
            copy_slab32(dbase + (uint32_t)((i + 3) & 3) * STG32,
                        qh + (long)sl * AT32, ql + (long)sl * AT32,
                        wh + (long)sl * BT32, wl + (long)sl * BT32, tid);
        } else {
            cp_commit();   // empty group to keep wait_group accounting uniform
        }

        uint32_t sb   = dbase + (uint32_t)(i & 3) * STG32;
        uint32_t ah_t = sb, al_t = sb + 8192, bh_t = sb + 16384, bl_t = sb + 32768;

        #pragma unroll
        for (int kk = 0; kk < 32; kk += 16) {
            uint32_t Bh[16], Bl[16];
            #pragma unroll
            for (int g = 0; g < 4; g++) {
                ldm_x4(&Bh[g * 4], ldm_addr64(bh_t, nw * 64 + g * 16, kk, lane));
                ldm_x4(&Bl[g * 4], ldm_addr64(bl_t, nw * 64 + g * 16, kk, lane));
            }
            #pragma unroll
            for (int mf = 0; mf < 4; mf++) {
                uint32_t Ah[4], Al[4];
                ldm_x4(Ah, ldm_addr64(ah_t, mw * 64 + mf * 16, kk, lane));
                ldm_x4(Al, ldm_addr64(al_t, mw * 64 + mf * 16, kk, lane));
                #pragma unroll
                for (int nf = 0; nf < 8; nf++) {
                    int g = nf >> 1, q = nf & 1;
                    uint32_t b0h = Bh[g * 4 + q], b1h = Bh[g * 4 + 2 + q];
                    uint32_t b0l = Bl[g * 4 + q], b1l = Bl[g * 4 + 2 + q];
                    mma16816(acc[mf][nf], Ah, b0h, b1h);   // hi*hi
                    mma16816(acc[mf][nf], Ah, b0l, b1l);   // hi*lo
                    mma16816(acc[mf][nf], Al, b0h, b1h);   // lo*hi
                }
            }
        }
    }

    // ---- epilogue: direct STG with fused bias ----
    long yb = (long)b * NTOT * (2 * DD);
    #pragma unroll
    for (int nf = 0; nf < 8; nf++) {
        int col = nt * 256 + nw * 64 + nf * 8 + (lane & 3) * 2;
        float bv0 = bias[b * 2 * DD + col];
        float bv1 = bias[b * 2 * DD + col + 1];
        #pragma unroll
        for (int mf = 0; mf < 4; mf++) {
            int r0 = mt * 128 + mw * 64 + mf * 16 + (lane >> 2);
            int r1 = r0 + 8;
            float* acp = acc[mf][nf];
            if (r0 < NTOT) {
                float2 v = make_float2(acp[0] + bv0, acp[1] + bv1);
                *(float2*)(Y + yb + (long)r0 * (2 * DD) + col) = v;
            }
            if (r1 < NTOT) {
                float2 v = make_float2(acp[2] + bv0, acp[3] + bv1);
                *(float2*)(Y + yb + (long)r1 * (2 * DD) + col) = v;
            }
        }
    }
}

// ---------------- group max over passages by table id -----------------------
__global__ void tmax_k(const int* __restrict__ tids)
{
    int b   = blockIdx.x / NTOK;
    int tok = blockIdx.x % NTOK;
    int d   = threadIdx.x;
    __shared__ int ids[NP];
    if (threadIdx.x < NP) ids[threadIdx.x] = tids[b * NP + threadIdx.x];
    float m[NTAB];
    #pragma unroll
    for (int t = 0; t < NTAB; t++) m[t] = -3.0e38f;
    __syncthreads();
    const float* Yb = g_Y + (long)b * NTOT * 2 * DD;
    for (int p = 0; p < NP; p++) {
        float v = Yb[(long)(p * NTOK + tok) * 2 * DD + d];
        int id = ids[p];
        #pragma unroll
        for (int t = 0; t < NTAB; t++)
            if (id == t) m[t] = fmaxf(m[t], v);
    }
    #pragma unroll
    for (int t = 0; t < NTAB; t++)
        g_tmax[(((long)b * NTAB + t) * NTOK + tok) * DD + d] = m[t];
}

// ---------------- final -----------------------------------------------------
__global__ void final_k(const float* __restrict__ masks, const int* __restrict__ tids,
                        const float* __restrict__ Wf2, const float* __restrict__ bf2,
                        float* __restrict__ out)
{
    int b = blockIdx.x / NP, p = blockIdx.x % NP;
    int tbl = tids[b * NP + p];
    __shared__ float w2[DD];
    __shared__ float ms[NTOK];
    __shared__ float red[256];
    for (int i = threadIdx.x; i < DD; i += blockDim.x) w2[i] = Wf2[i];
    if (threadIdx.x < NTOK) ms[threadIdx.x] = masks[(b * NP + p) * NTOK + threadIdx.x];
    __syncthreads();

    const float* p1 = g_Y + ((long)b * NTOT + (long)p * NTOK) * 2 * DD + DD;
    const float* p2 = g_p2 + ((long)b * NTAB + tbl) * NTOK * DD;
    float bv = bf2[0];
    float acc = 0.f;
    for (int idx = threadIdx.x; idx < NTOK * DD; idx += blockDim.x) {
        int tok = idx / DD, d = idx % DD;
        float v = p1[(long)tok * 2 * DD + d] + p2[tok * DD + d];
        float s = ms[tok] * w2[d] * fmaxf(v, 0.f);
        if (d == 0) s += bv * ms[tok];
        acc += s;
    }
    red[threadIdx.x] = acc;
    __syncthreads();
    for (int s = 128; s > 0; s >>= 1) {
        if (threadIdx.x < s) red[threadIdx.x] += red[threadIdx.x + s];
        __syncthreads();
    }
    if (threadIdx.x == 0) out[b * NP + p] = red[0];
}

// ---------------- launcher --------------------------------------------------
extern "C" void kernel_launch(void* const* d_in, const int* in_sizes, int n_in,
                              void* d_out, int out_size)
{
    const float* ans   = (const float*)d_in[0];
    const float* qps   = (const float*)d_in[1];
    const float* masks = (const float*)d_in[2];
    const int*   tids  = (const int*)  d_in[3];
    const float* Wp    = (const float*)d_in[4];
    const float* bp    = (const float*)d_in[5];
    const float* Wt    = (const float*)d_in[6];
    const float* bt    = (const float*)d_in[7];
    const float* Wf1   = (const float*)d_in[8];
    const float* bf1   = (const float*)d_in[9];
    const float* Wf2   = (const float*)d_in[10];
    const float* bf2   = (const float*)d_in[11];
    float* out = (float*)d_out;

    void *pG, *pBias, *pY, *pTmax, *pP2;
    cudaGetSymbolAddress(&pG,    g_G);
    cudaGetSymbolAddress(&pBias, g_bias);
    cudaGetSymbolAddress(&pY,    g_Y);
    cudaGetSymbolAddress(&pTmax, g_tmax);
    cudaGetSymbolAddress(&pP2,   g_p2);

    // 1) G = Wf1_p @ [Wp_Q | Wp_AQ]
    gemm_k<<<dim3(1536 / 128, 768 / 128, 1), 256>>>(
        Wf1, 2 * DD, 0,
        Wp + DD, 1, 3 * DD, 0,
        (const float*)nullptr, 0,
        (float*)pG, 2 * DD, 0,
        DD, 2 * DD, DD);

    // 2) per-batch c_p, c_t ; 3) u
    prep1_k<<<dim3(3, BQ), 256>>>(ans, Wp, bp, Wt, bt);
    prep_u_k<<<dim3(3, BQ), 256>>>(Wf1, bf1);

    // 4) prepack Q and Wbig as SW64 bf16 hi/lo tile images
    {
        long tq = (long)BQ * MT * 128 * 96;
        qsplit_k<<<(unsigned)((tq + 255) / 256), 256>>>(qps);
        long tw = (long)BQ * NT * 256 * 96;
        wsplit_k<<<(unsigned)((tw + 255) / 256), 256>>>(ans, Wt);
    }

    // 5) main GEMM via mma.sync (bf16x3 split), 4-stage cp.async pipeline
    {
        int dyn = 4 * STG32;   // 192KB
        cudaFuncSetAttribute(tgemm_k, cudaFuncAttributeMaxDynamicSharedMemorySize, dyn);
        tgemm_k<<<dim3(NT, MT, BQ), 256, dyn>>>((const float*)pBias, (float*)pY);
    }

    // 6) table group-max
    tmax_k<<<BQ * NTOK, DD>>>(tids);

    // 7) part2 = tmax @ Wf1_a^T
    gemm_k<<<dim3(768 / 128, (NTAB * NTOK + 127) / 128, BQ), 256>>>(
        (const float*)pTmax, DD, (long)NTAB * NTOK * DD,
        Wf1 + DD, 2 * DD, 1, 0,
        (const float*)nullptr, 0,
        (float*)pP2, DD, (long)NTAB * NTOK * DD,
        NTAB * NTOK, DD, DD);

    // 8) final masked reduction
    final_k<<<BQ * NP, 256>>>(masks, tids, Wf2, bf2, out);
}

// round 5
// speedup vs baseline: 1.9979x; 1.1469x over previous
#include <cuda_runtime.h>
#include <cuda_fp16.h>
#include <cstdint>

// Problem constants (fixed by setup_inputs)
#define BQ   4
#define NLYR 2
#define NP   100
#define NTOK 60
#define NTOT 6000
#define DD   768
#define NTAB 10

#define MT   47          // m tiles of 128 (6016 >= 6000)
#define NT   6           // n tiles of 256 (1536)
#define NS32 24          // k slabs of 32
#define AT32 8192        // 128 rows x 32 k fp16 = 8KB
#define BT32 16384       // 256 rows x 32 k fp16 = 16KB
#define STG32 32768      // stage: Ahi + Alo + Bhi = 8+8+16 KB

// ---------------- scratch ---------------------------------------------------
__device__ float g_G[DD * 2 * DD];
__device__ float g_cp[BQ * DD];
__device__ float g_bias[BQ * 2 * DD];
__device__ float g_Y[(size_t)BQ * NTOT * 2 * DD];
__device__ float g_tmax[BQ * NTAB * NTOK * DD];
__device__ float g_p2[BQ * NTAB * NTOK * DD];
// pre-swizzled fp16 tile images (SW64, 64B rows, 32-k slabs)
__device__ unsigned char g_Qhi[(size_t)BQ * MT * NS32 * AT32];
__device__ unsigned char g_Qlo[(size_t)BQ * MT * NS32 * AT32];
__device__ unsigned char g_Whi[(size_t)BQ * NT * NS32 * BT32];

// ---------------- PTX helpers ----------------------------------------------
__device__ __forceinline__ uint32_t smem_u32(const void* p) {
    uint32_t a;
    asm("{ .reg .u64 t; cvta.to.shared.u64 t, %1; cvt.u32.u64 %0, t; }" : "=r"(a) : "l"(p));
    return a;
}
__device__ __forceinline__ void cpasync16(uint32_t dst, const void* src) {
    asm volatile("cp.async.cg.shared.global [%0], [%1], 16;" :: "r"(dst), "l"(src));
}
__device__ __forceinline__ void cp_commit() {
    asm volatile("cp.async.commit_group;" ::: "memory");
}
__device__ __forceinline__ void ldm_x4(uint32_t* r, uint32_t addr) {
    asm volatile("ldmatrix.sync.aligned.m8n8.x4.shared.b16 {%0,%1,%2,%3}, [%4];"
                 : "=r"(r[0]), "=r"(r[1]), "=r"(r[2]), "=r"(r[3]) : "r"(addr));
}
__device__ __forceinline__ void mma16816(float* d, const uint32_t* a,
                                         uint32_t b0, uint32_t b1) {
    asm volatile(
        "mma.sync.aligned.m16n8k16.row.col.f32.f16.f16.f32 "
        "{%0,%1,%2,%3}, {%4,%5,%6,%7}, {%8,%9}, {%0,%1,%2,%3};"
        : "+f"(d[0]), "+f"(d[1]), "+f"(d[2]), "+f"(d[3])
        : "r"(a[0]), "r"(a[1]), "r"(a[2]), "r"(a[3]), "r"(b0), "r"(b1));
}
// SW64-swizzled ldmatrix lane address within a (rows x 32k) fp16 tile, 64B rows
__device__ __forceinline__ uint32_t ldm_addr64(uint32_t tilebase, int row0, int k0, int lane) {
    int row = row0 + (lane & 15);
    int kc  = k0 + ((lane >> 4) << 3);
    uint32_t off = (uint32_t)(row * 64 + kc * 2);
    off ^= (off >> 3) & 0x30;
    return tilebase + off;
}
__device__ __forceinline__ uint32_t swz64(uint32_t off) {
    return off ^ ((off >> 3) & 0x30);
}

// ---------------- SIMT GEMM (small ops) -------------------------------------
__global__ __launch_bounds__(256)
void gemm_k(const float* __restrict__ A, long a_rs, long a_bs,
            const float* __restrict__ Bm, long b_ns, long b_ks, long b_bs,
            const float* __restrict__ bias, long bias_bs,
            float* __restrict__ C, long c_ld, long c_bs,
            int M, int N, int K)
{
    const int BM = 128, BN = 128, BK = 16;
    __shared__ float As[BK][BM + 4];
    __shared__ float Bs[BK][BN + 4];
    int bz = blockIdx.z;
    const float* Ab = A  + (long)bz * a_bs;
    const float* Bb = Bm + (long)bz * b_bs;
    float*       Cb = C  + (long)bz * c_bs;
    int m0 = blockIdx.y * BM, n0 = blockIdx.x * BN;
    int tid = threadIdx.x, tx = tid & 15, ty = tid >> 4;
    float acc[8][8];
    #pragma unroll
    for (int i = 0; i < 8; i++)
        #pragma unroll
        for (int j = 0; j < 8; j++) acc[i][j] = 0.f;
    for (int k0 = 0; k0 < K; k0 += BK) {
        #pragma unroll
        for (int i = 0; i < 8; i++) {
            int e = tid + i * 256, m = e >> 4, k = e & 15;
            float v = 0.f;
            if (m0 + m < M) v = Ab[(long)(m0 + m) * a_rs + (k0 + k)];
            As[k][m] = v;
        }
        #pragma unroll
        for (int i = 0; i < 8; i++) {
            int e = tid + i * 256, n = e >> 4, k = e & 15;
            Bs[k][n] = Bb[(long)(n0 + n) * b_ns + (long)(k0 + k) * b_ks];
        }
        __syncthreads();
        #pragma unroll
        for (int kk = 0; kk < BK; kk++) {
            float a[8], bb[8];
            #pragma unroll
            for (int i = 0; i < 8; i++) a[i]  = As[kk][ty * 8 + i];
            #pragma unroll
            for (int j = 0; j < 8; j++) bb[j] = Bs[kk][tx * 8 + j];
            #pragma unroll
            for (int i = 0; i < 8; i++)
                #pragma unroll
                for (int j = 0; j < 8; j++) acc[i][j] += a[i] * bb[j];
        }
        __syncthreads();
    }
    #pragma unroll
    for (int i = 0; i < 8; i++) {
        int m = m0 + ty * 8 + i;
        if (m < M) {
            #pragma unroll
            for (int j = 0; j < 8; j++) {
                int n = n0 + tx * 8 + j;
                float v = acc[i][j];
                if (bias) v += bias[(long)bz * bias_bs + n];
                Cb[(long)m * c_ld + n] = v;
            }
        }
    }
}

// ---------------- prep kernels ----------------------------------------------
__global__ void prep1_k(const float* __restrict__ ans, const float* __restrict__ Wp,
                        const float* __restrict__ bp, const float* __restrict__ Wt,
                        const float* __restrict__ bt)
{
    int b = blockIdx.y;
    int d = blockIdx.x * blockDim.x + threadIdx.x;
    const float* Av = ans + (long)(b * NLYR + (NLYR - 1)) * DD;
    float sp = bp[d], st = bt[d];
    const float* wpr = Wp + (long)d * 3 * DD;
    const float* wtr = Wt + (long)d * 3 * DD;
    for (int k = 0; k < DD; k++) {
        float a = Av[k];
        sp += wpr[k] * a;
        st += wtr[k] * a;
    }
    g_cp[b * DD + d] = sp;
    g_bias[b * 2 * DD + d] = st;
}

__global__ void prep_u_k(const float* __restrict__ Wf1, const float* __restrict__ bf1)
{
    int b = blockIdx.y;
    int d = blockIdx.x * blockDim.x + threadIdx.x;
    const float* cp = g_cp + b * DD;
    const float* wr = Wf1 + (long)d * 2 * DD;
    float s = bf1[d];
    for (int k = 0; k < DD; k++) s += wr[k] * cp[k];
    g_bias[b * 2 * DD + DD + d] = s;
}

// ---------------- fp16 split helpers ----------------------------------------
__device__ __forceinline__ void split8h(const float* v, uint4& hi, uint4& lo) {
    unsigned short h[8], l[8];
    #pragma unroll
    for (int i = 0; i < 8; i++) {
        __half hh = __float2half_rn(v[i]);
        float r = v[i] - __half2float(hh);
        __half hl = __float2half_rn(r);
        h[i] = __half_as_ushort(hh);
        l[i] = __half_as_ushort(hl);
    }
    hi.x = h[0] | ((uint32_t)h[1] << 16); hi.y = h[2] | ((uint32_t)h[3] << 16);
    hi.z = h[4] | ((uint32_t)h[5] << 16); hi.w = h[6] | ((uint32_t)h[7] << 16);
    lo.x = l[0] | ((uint32_t)l[1] << 16); lo.y = l[2] | ((uint32_t)l[3] << 16);
    lo.z = l[4] | ((uint32_t)l[5] << 16); lo.w = l[6] | ((uint32_t)l[7] << 16);
}
__device__ __forceinline__ uint4 pack8h(const float* v) {
    unsigned short h[8];
    #pragma unroll
    for (int i = 0; i < 8; i++) h[i] = __half_as_ushort(__float2half_rn(v[i]));
    uint4 r;
    r.x = h[0] | ((uint32_t)h[1] << 16); r.y = h[2] | ((uint32_t)h[3] << 16);
    r.z = h[4] | ((uint32_t)h[5] << 16); r.w = h[6] | ((uint32_t)h[7] << 16);
    return r;
}

// Q -> SW64 fp16 hi/lo tile images. thread = (b, mt, r, c8)
__global__ __launch_bounds__(256) void qsplit_k(const float* __restrict__ qps)
{
    long idx = (long)blockIdx.x * 256 + threadIdx.x;
    int c8 = (int)(idx % 96);
    long t  = idx / 96;
    int r  = (int)(t % 128);
    t /= 128;
    int mt = (int)(t % MT);
    int b  = (int)(t / MT);
    if (b >= BQ) return;
    int m = mt * 128 + r;
    int k0 = c8 * 8;
    float v[8];
    if (m < NTOT) {
        const float* src = qps + ((long)(b * NLYR + 1) * NTOT + m) * DD + k0;
        float4 a = ((const float4*)src)[0];
        float4 c = ((const float4*)src)[1];
        v[0]=a.x; v[1]=a.y; v[2]=a.z; v[3]=a.w; v[4]=c.x; v[5]=c.y; v[6]=c.z; v[7]=c.w;
    } else {
        #pragma unroll
        for (int i = 0; i < 8; i++) v[i] = 0.f;
    }
    uint4 hi, lo;
    split8h(v, hi, lo);
    int slab = k0 >> 5, kin = k0 & 31;
    uint32_t off = swz64((uint32_t)(r * 64 + kin * 2));
    long base = ((long)(b * MT + mt) * NS32 + slab) * AT32 + off;
    *(uint4*)(g_Qhi + base) = hi;
    *(uint4*)(g_Qlo + base) = lo;
}

// Wbig -> SW64 fp16 hi tile image. thread = (b, nt, r, c8)
__global__ __launch_bounds__(256) void wsplit_k(const float* __restrict__ ans,
                                                const float* __restrict__ Wt)
{
    long idx = (long)blockIdx.x * 256 + threadIdx.x;
    int c8 = (int)(idx % 96);
    long t  = idx / 96;
    int r  = (int)(t % 256);
    t /= 256;
    int nt = (int)(t % NT);
    int b  = (int)(t / NT);
    if (b >= BQ) return;
    int j = nt * 256 + r;
    int k0 = c8 * 8;
    const float* Av = ans + (long)(b * NLYR + 1) * DD + k0;
    float a[8], w1[8], w2[8];
    {
        float4 x = ((const float4*)Av)[0], y = ((const float4*)Av)[1];
        a[0]=x.x; a[1]=x.y; a[2]=x.z; a[3]=x.w; a[4]=y.x; a[5]=y.y; a[6]=y.z; a[7]=y.w;
    }
    if (j < DD) {
        const float* wr = Wt + (long)j * 3 * DD;
        float4 x = *(const float4*)(wr + DD + k0),     y = *(const float4*)(wr + DD + k0 + 4);
        float4 u = *(const float4*)(wr + 2 * DD + k0), w = *(const float4*)(wr + 2 * DD + k0 + 4);
        w1[0]=x.x; w1[1]=x.y; w1[2]=x.z; w1[3]=x.w; w1[4]=y.x; w1[5]=y.y; w1[6]=y.z; w1[7]=y.w;
        w2[0]=u.x; w2[1]=u.y; w2[2]=u.z; w2[3]=u.w; w2[4]=w.x; w2[5]=w.y; w2[6]=w.z; w2[7]=w.w;
    } else {
        int d = j - DD;
        const float* gr = g_G + (long)d * 2 * DD;
        float4 x = *(const float4*)(gr + k0),      y = *(const float4*)(gr + k0 + 4);
        float4 u = *(const float4*)(gr + DD + k0), w = *(const float4*)(gr + DD + k0 + 4);
        w1[0]=x.x; w1[1]=x.y; w1[2]=x.z; w1[3]=x.w; w1[4]=y.x; w1[5]=y.y; w1[6]=y.z; w1[7]=y.w;
        w2[0]=u.x; w2[1]=u.y; w2[2]=u.z; w2[3]=u.w; w2[4]=w.x; w2[5]=w.y; w2[6]=w.z; w2[7]=w.w;
    }
    float v[8];
    #pragma unroll
    for (int i = 0; i < 8; i++) v[i] = w1[i] + w2[i] * a[i];
    uint4 hi = pack8h(v);
    int slab = k0 >> 5, kin = k0 & 31;
    uint32_t off = swz64((uint32_t)(r * 64 + kin * 2));
    long base = ((long)(b * NT + nt) * NS32 + slab) * BT32 + off;
    *(uint4*)(g_Whi + base) = hi;
}

// ---------------- HMMA main GEMM --------------------------------------------
// stage layout: [Ahi 8K][Alo 8K][Bhi 16K] = 32KB
__device__ __forceinline__ void copy_slab32(uint32_t sb,
    const unsigned char* qh, const unsigned char* ql,
    const unsigned char* wh, int tid)
{
    int o = tid * 16;   // 256 threads * 16B = 4KB per sweep
    #pragma unroll
    for (int t = 0; t < 2; t++) cpasync16(sb + o + t * 4096,              qh + o + t * 4096);
    #pragma unroll
    for (int t = 0; t < 2; t++) cpasync16(sb + 8192 + o + t * 4096,       ql + o + t * 4096);
    #pragma unroll
    for (int t = 0; t < 4; t++) cpasync16(sb + 16384 + o + t * 4096,      wh + o + t * 4096);
    cp_commit();
}

__global__ __launch_bounds__(256, 1)
void tgemm_k(const float* __restrict__ bias, float* __restrict__ Y)
{
    extern __shared__ __align__(1024) unsigned char dsm[];
    uint32_t dbase = smem_u32(dsm);

    int tid  = threadIdx.x;
    int lane = tid & 31;
    int w    = tid >> 5;
    int mw   = w >> 2;        // 0..1 : 64-row block
    int nw   = w & 3;         // 0..3 : 64-col block
    int b    = blockIdx.z;
    int nt   = blockIdx.x;    // 0..5 (256-col tiles)
    int mt   = blockIdx.y;    // 0..46

    const unsigned char* qh = g_Qhi + ((long)(b * MT + mt) * NS32) * AT32;
    const unsigned char* ql = g_Qlo + ((long)(b * MT + mt) * NS32) * AT32;
    const unsigned char* wh = g_Whi + ((long)(b * NT + nt) * NS32) * BT32;

    float acc[4][8][4];
    #pragma unroll
    for (int i = 0; i < 4; i++)
        #pragma unroll
        for (int j = 0; j < 8; j++)
            #pragma unroll
            for (int k = 0; k < 4; k++) acc[i][j][k] = 0.f;

    // prologue: stages 0,1,2
    copy_slab32(dbase,             qh,            ql,            wh,            tid);
    copy_slab32(dbase + STG32,     qh + AT32,     ql + AT32,     wh + BT32,     tid);
    copy_slab32(dbase + 2 * STG32, qh + 2 * AT32, ql + 2 * AT32, wh + 2 * BT32, tid);

    for (int i = 0; i < NS32; i++) {
        asm volatile("cp.async.wait_group 2;" ::: "memory");
        __syncthreads();
        if (i + 3 < NS32) {
            int sl = i + 3;
            copy_slab32(dbase + (uint32_t)((i + 3) & 3) * STG32,
                        qh + (long)sl * AT32, ql + (long)sl * AT32,
                        wh + (long)sl * BT32, tid);
        } else {
            cp_commit();   // empty group to keep wait_group accounting uniform
        }

        uint32_t sb   = dbase + (uint32_t)(i & 3) * STG32;
        uint32_t ah_t = sb, al_t = sb + 8192, bh_t = sb + 16384;

        #pragma unroll
        for (int kk = 0; kk < 32; kk += 16) {
            uint32_t Bh[16];
            #pragma unroll
            for (int g = 0; g < 4; g++)
                ldm_x4(&Bh[g * 4], ldm_addr64(bh_t, nw * 64 + g * 16, kk, lane));
            #pragma unroll
            for (int mf = 0; mf < 4; mf++) {
                uint32_t Ah[4], Al[4];
                ldm_x4(Ah, ldm_addr64(ah_t, mw * 64 + mf * 16, kk, lane));
                ldm_x4(Al, ldm_addr64(al_t, mw * 64 + mf * 16, kk, lane));
                #pragma unroll
                for (int nf = 0; nf < 8; nf++) {
                    int g = nf >> 1, q = nf & 1;
                    uint32_t b0h = Bh[g * 4 + q], b1h = Bh[g * 4 + 2 + q];
                    mma16816(acc[mf][nf], Ah, b0h, b1h);   // hi*hi
                    mma16816(acc[mf][nf], Al, b0h, b1h);   // lo*hi
                }
            }
        }
    }

    // ---- epilogue: direct STG with fused bias ----
    long yb = (long)b * NTOT * (2 * DD);
    #pragma unroll
    for (int nf = 0; nf < 8; nf++) {
        int col = nt * 256 + nw * 64 + nf * 8 + (lane & 3) * 2;
        float bv0 = bias[b * 2 * DD + col];
        float bv1 = bias[b * 2 * DD + col + 1];
        #pragma unroll
        for (int mf = 0; mf < 4; mf++) {
            int r0 = mt * 128 + mw * 64 + mf * 16 + (lane >> 2);
            int r1 = r0 + 8;
            float* acp = acc[mf][nf];
            if (r0 < NTOT) {
                float2 v = make_float2(acp[0] + bv0, acp[1] + bv1);
                *(float2*)(Y + yb + (long)r0 * (2 * DD) + col) = v;
            }
            if (r1 < NTOT) {
                float2 v = make_float2(acp[2] + bv0, acp[3] + bv1);
                *(float2*)(Y + yb + (long)r1 * (2 * DD) + col) = v;
            }
        }
    }
}

// ---------------- group max over passages by table id -----------------------
__global__ void tmax_k(const int* __restrict__ tids)
{
    int b   = blockIdx.x / NTOK;
    int tok = blockIdx.x % NTOK;
    int d   = threadIdx.x;
    __shared__ int ids[NP];
    if (threadIdx.x < NP) ids[threadIdx.x] = tids[b * NP + threadIdx.x];
    float m[NTAB];
    #pragma unroll
    for (int t = 0; t < NTAB; t++) m[t] = -3.0e38f;
    __syncthreads();
    const float* Yb = g_Y + (long)b * NTOT * 2 * DD;
    for (int p = 0; p < NP; p++) {
        float v = Yb[(long)(p * NTOK + tok) * 2 * DD + d];
        int id = ids[p];
        #pragma unroll
        for (int t = 0; t < NTAB; t++)
            if (id == t) m[t] = fmaxf(m[t], v);
    }
    #pragma unroll
    for (int t = 0; t < NTAB; t++)
        g_tmax[(((long)b * NTAB + t) * NTOK + tok) * DD + d] = m[t];
}

// ---------------- final -----------------------------------------------------
__global__ void final_k(const float* __restrict__ masks, const int* __restrict__ tids,
                        const float* __restrict__ Wf2, const float* __restrict__ bf2,
                        float* __restrict__ out)
{
    int b = blockIdx.x / NP, p = blockIdx.x % NP;
    int tbl = tids[b * NP + p];
    __shared__ float w2[DD];
    __shared__ float ms[NTOK];
    __shared__ float red[256];
    for (int i = threadIdx.x; i < DD; i += blockDim.x) w2[i] = Wf2[i];
    if (threadIdx.x < NTOK) ms[threadIdx.x] = masks[(b * NP + p) * NTOK + threadIdx.x];
    __syncthreads();

    const float* p1 = g_Y + ((long)b * NTOT + (long)p * NTOK) * 2 * DD + DD;
    const float* p2 = g_p2 + ((long)b * NTAB + tbl) * NTOK * DD;
    float bv = bf2[0];
    float acc = 0.f;
    for (int idx = threadIdx.x; idx < NTOK * DD; idx += blockDim.x) {
        int tok = idx / DD, d = idx % DD;
        float v = p1[(long)tok * 2 * DD + d] + p2[tok * DD + d];
        float s = ms[tok] * w2[d] * fmaxf(v, 0.f);
        if (d == 0) s += bv * ms[tok];
        acc += s;
    }
    red[threadIdx.x] = acc;
    __syncthreads();
    for (int s = 128; s > 0; s >>= 1) {
        if (threadIdx.x < s) red[threadIdx.x] += red[threadIdx.x + s];
        __syncthreads();
    }
    if (threadIdx.x == 0) out[b * NP + p] = red[0];
}

// ---------------- launcher --------------------------------------------------
extern "C" void kernel_launch(void* const* d_in, const int* in_sizes, int n_in,
                              void* d_out, int out_size)
{
    const float* ans   = (const float*)d_in[0];
    const float* qps   = (const float*)d_in[1];
    const float* masks = (const float*)d_in[2];
    const int*   tids  = (const int*)  d_in[3];
    const float* Wp    = (const float*)d_in[4];
    const float* bp    = (const float*)d_in[5];
    const float* Wt    = (const float*)d_in[6];
    const float* bt    = (const float*)d_in[7];
    const float* Wf1   = (const float*)d_in[8];
    const float* bf1   = (const float*)d_in[9];
    const float* Wf2   = (const float*)d_in[10];
    const float* bf2   = (const float*)d_in[11];
    float* out = (float*)d_out;

    void *pG, *pBias, *pY, *pTmax, *pP2;
    cudaGetSymbolAddress(&pG,    g_G);
    cudaGetSymbolAddress(&pBias, g_bias);
    cudaGetSymbolAddress(&pY,    g_Y);
    cudaGetSymbolAddress(&pTmax, g_tmax);
    cudaGetSymbolAddress(&pP2,   g_p2);

    // 1) G = Wf1_p @ [Wp_Q | Wp_AQ]
    gemm_k<<<dim3(1536 / 128, 768 / 128, 1), 256>>>(
        Wf1, 2 * DD, 0,
        Wp + DD, 1, 3 * DD, 0,
        (const float*)nullptr, 0,
        (float*)pG, 2 * DD, 0,
        DD, 2 * DD, DD);

    // 2) per-batch c_p, c_t ; 3) u
    prep1_k<<<dim3(3, BQ), 256>>>(ans, Wp, bp, Wt, bt);
    prep_u_k<<<dim3(3, BQ), 256>>>(Wf1, bf1);

    // 4) prepack Q (hi/lo) and Wbig (hi) as SW64 fp16 tile images
    {
        long tq = (long)BQ * MT * 128 * 96;
        qsplit_k<<<(unsigned)((tq + 255) / 256), 256>>>(qps);
        long tw = (long)BQ * NT * 256 * 96;
        wsplit_k<<<(unsigned)((tw + 255) / 256), 256>>>(ans, Wt);
    }

    // 5) main GEMM via mma.sync (fp16x2 split), 4-stage cp.async pipeline
    {
        int dyn = 4 * STG32;   // 128KB
        cudaFuncSetAttribute(tgemm_k, cudaFuncAttributeMaxDynamicSharedMemorySize, dyn);
        tgemm_k<<<dim3(NT, MT, BQ), 256, dyn>>>((const float*)pBias, (float*)pY);
    }

    // 6) table group-max
    tmax_k<<<BQ * NTOK, DD>>>(tids);

    // 7) part2 = tmax @ Wf1_a^T
    gemm_k<<<dim3(768 / 128, (NTAB * NTOK + 127) / 128, BQ), 256>>>(
        (const float*)pTmax, DD, (long)NTAB * NTOK * DD,
        Wf1 + DD, 2 * DD, 1, 0,
        (const float*)nullptr, 0,
        (float*)pP2, DD, (long)NTAB * NTOK * DD,
        NTAB * NTOK, DD, DD);

    // 8) final masked reduction
    final_k<<<BQ * NP, 256>>>(masks, tids, Wf2, bf2, out);
}

// round 6
// speedup vs baseline: 2.2705x; 1.1365x over previous
#include <cuda_runtime.h>
#include <cuda_fp16.h>
#include <cstdint>

// Problem constants (fixed by setup_inputs)
#define BQ   4
#define NLYR 2
#define NP   100
#define NTOK 60
#define NTOT 6000
#define DD   768
#define NTAB 10

#define MT   47          // m tiles of 128 (6016 >= 6000)
#define NT   6           // n tiles of 256 (1536)
#define NS64 12          // k slabs of 64
#define AT64 16384       // 128 rows x 64 k fp16 = 16KB
#define BT64 32768       // 256 rows x 64 k fp16 = 32KB
#define STG64 49152      // stage: A + B = 48KB

// ---------------- scratch ---------------------------------------------------
__device__ float g_G[DD * 2 * DD];
__device__ float g_cp[BQ * DD];
__device__ float g_bias[BQ * 2 * DD];
__device__ float g_Y[(size_t)BQ * NTOT * 2 * DD];
__device__ float g_tmax[BQ * NTAB * NTOK * DD];
__device__ float g_p2[BQ * NTAB * NTOK * DD];
// pre-swizzled fp16 tile images (SW128, 128B rows, 64-k slabs)
__device__ unsigned char g_Qh[(size_t)BQ * MT * NS64 * AT64];
__device__ unsigned char g_Wh[(size_t)BQ * NT * NS64 * BT64];

// ---------------- PTX helpers ----------------------------------------------
__device__ __forceinline__ uint32_t smem_u32(const void* p) {
    uint32_t a;
    asm("{ .reg .u64 t; cvta.to.shared.u64 t, %1; cvt.u32.u64 %0, t; }" : "=r"(a) : "l"(p));
    return a;
}
__device__ __forceinline__ void cpasync16(uint32_t dst, const void* src) {
    asm volatile("cp.async.cg.shared.global [%0], [%1], 16;" :: "r"(dst), "l"(src));
}
__device__ __forceinline__ void cp_commit() {
    asm volatile("cp.async.commit_group;" ::: "memory");
}
__device__ __forceinline__ void ldm_x4(uint32_t* r, uint32_t addr) {
    asm volatile("ldmatrix.sync.aligned.m8n8.x4.shared.b16 {%0,%1,%2,%3}, [%4];"
                 : "=r"(r[0]), "=r"(r[1]), "=r"(r[2]), "=r"(r[3]) : "r"(addr));
}
__device__ __forceinline__ void mma16816(float* d, const uint32_t* a,
                                         uint32_t b0, uint32_t b1) {
    asm volatile(
        "mma.sync.aligned.m16n8k16.row.col.f32.f16.f16.f32 "
        "{%0,%1,%2,%3}, {%4,%5,%6,%7}, {%8,%9}, {%0,%1,%2,%3};"
        : "+f"(d[0]), "+f"(d[1]), "+f"(d[2]), "+f"(d[3])
        : "r"(a[0]), "r"(a[1]), "r"(a[2]), "r"(a[3]), "r"(b0), "r"(b1));
}
// SW128-swizzled ldmatrix lane address within a (rows x 64k) fp16 tile, 128B rows
__device__ __forceinline__ uint32_t ldm_addr128(uint32_t tilebase, int row0, int k0, int lane) {
    int row = row0 + (lane & 15);
    int kc  = k0 + ((lane >> 4) << 3);
    uint32_t off = (uint32_t)(row * 128 + kc * 2);
    off ^= (off >> 3) & 0x70;
    return tilebase + off;
}
__device__ __forceinline__ uint32_t swz128(uint32_t off) {
    return off ^ ((off >> 3) & 0x70);
}

// ---------------- SIMT GEMM (small ops) -------------------------------------
__global__ __launch_bounds__(256)
void gemm_k(const float* __restrict__ A, long a_rs, long a_bs,
            const float* __restrict__ Bm, long b_ns, long b_ks, long b_bs,
            const float* __restrict__ bias, long bias_bs,
            float* __restrict__ C, long c_ld, long c_bs,
            int M, int N, int K)
{
    const int BM = 128, BN = 128, BK = 16;
    __shared__ float As[BK][BM + 4];
    __shared__ float Bs[BK][BN + 4];
    int bz = blockIdx.z;
    const float* Ab = A  + (long)bz * a_bs;
    const float* Bb = Bm + (long)bz * b_bs;
    float*       Cb = C  + (long)bz * c_bs;
    int m0 = blockIdx.y * BM, n0 = blockIdx.x * BN;
    int tid = threadIdx.x, tx = tid & 15, ty = tid >> 4;
    float acc[8][8];
    #pragma unroll
    for (int i = 0; i < 8; i++)
        #pragma unroll
        for (int j = 0; j < 8; j++) acc[i][j] = 0.f;
    for (int k0 = 0; k0 < K; k0 += BK) {
        #pragma unroll
        for (int i = 0; i < 8; i++) {
            int e = tid + i * 256, m = e >> 4, k = e & 15;
            float v = 0.f;
            if (m0 + m < M) v = Ab[(long)(m0 + m) * a_rs + (k0 + k)];
            As[k][m] = v;
        }
        if (b_ks == 1) {
            // k contiguous in memory: k-fastest mapping coalesces
            #pragma unroll
            for (int i = 0; i < 8; i++) {
                int e = tid + i * 256, n = e >> 4, k = e & 15;
                Bs[k][n] = Bb[(long)(n0 + n) * b_ns + (long)(k0 + k) * b_ks];
            }
        } else {
            // n contiguous in memory: n-fastest mapping coalesces
            #pragma unroll
            for (int i = 0; i < 8; i++) {
                int e = tid + i * 256, k = e >> 7, n = e & 127;
                Bs[k][n] = Bb[(long)(n0 + n) * b_ns + (long)(k0 + k) * b_ks];
            }
        }
        __syncthreads();
        #pragma unroll
        for (int kk = 0; kk < BK; kk++) {
            float a[8], bb[8];
            #pragma unroll
            for (int i = 0; i < 8; i++) a[i]  = As[kk][ty * 8 + i];
            #pragma unroll
            for (int j = 0; j < 8; j++) bb[j] = Bs[kk][tx * 8 + j];
            #pragma unroll
            for (int i = 0; i < 8; i++)
                #pragma unroll
                for (int j = 0; j < 8; j++) acc[i][j] += a[i] * bb[j];
        }
        __syncthreads();
    }
    #pragma unroll
    for (int i = 0; i < 8; i++) {
        int m = m0 + ty * 8 + i;
        if (m < M) {
            #pragma unroll
            for (int j = 0; j < 8; j++) {
                int n = n0 + tx * 8 + j;
                float v = acc[i][j];
                if (bias) v += bias[(long)bz * bias_bs + n];
                Cb[(long)m * c_ld + n] = v;
            }
        }
    }
}

// ---------------- prep kernels ----------------------------------------------
__global__ void prep1_k(const float* __restrict__ ans, const float* __restrict__ Wp,
                        const float* __restrict__ bp, const float* __restrict__ Wt,
                        const float* __restrict__ bt)
{
    int b = blockIdx.y;
    int d = blockIdx.x * blockDim.x + threadIdx.x;
    const float* Av = ans + (long)(b * NLYR + (NLYR - 1)) * DD;
    float sp = bp[d], st = bt[d];
    const float* wpr = Wp + (long)d * 3 * DD;
    const float* wtr = Wt + (long)d * 3 * DD;
    for (int k = 0; k < DD; k++) {
        float a = Av[k];
        sp += wpr[k] * a;
        st += wtr[k] * a;
    }
    g_cp[b * DD + d] = sp;
    g_bias[b * 2 * DD + d] = st;
}

__global__ void prep_u_k(const float* __restrict__ Wf1, const float* __restrict__ bf1)
{
    int b = blockIdx.y;
    int d = blockIdx.x * blockDim.x + threadIdx.x;
    const float* cp = g_cp + b * DD;
    const float* wr = Wf1 + (long)d * 2 * DD;
    float s = bf1[d];
    for (int k = 0; k < DD; k++) s += wr[k] * cp[k];
    g_bias[b * 2 * DD + DD + d] = s;
}

// ---------------- fp16 pack helper ------------------------------------------
__device__ __forceinline__ uint4 pack8h(const float* v) {
    unsigned short h[8];
    #pragma unroll
    for (int i = 0; i < 8; i++) h[i] = __half_as_ushort(__float2half_rn(v[i]));
    uint4 r;
    r.x = h[0] | ((uint32_t)h[1] << 16); r.y = h[2] | ((uint32_t)h[3] << 16);
    r.z = h[4] | ((uint32_t)h[5] << 16); r.w = h[6] | ((uint32_t)h[7] << 16);
    return r;
}

// Q -> SW128 fp16 tile image. thread = (b, mt, r, c8)
__global__ __launch_bounds__(256) void qsplit_k(const float* __restrict__ qps)
{
    long idx = (long)blockIdx.x * 256 + threadIdx.x;
    int c8 = (int)(idx % 96);
    long t  = idx / 96;
    int r  = (int)(t % 128);
    t /= 128;
    int mt = (int)(t % MT);
    int b  = (int)(t / MT);
    if (b >= BQ) return;
    int m = mt * 128 + r;
    int k0 = c8 * 8;
    float v[8];
    if (m < NTOT) {
        const float* src = qps + ((long)(b * NLYR + 1) * NTOT + m) * DD + k0;
        float4 a = ((const float4*)src)[0];
        float4 c = ((const float4*)src)[1];
        v[0]=a.x; v[1]=a.y; v[2]=a.z; v[3]=a.w; v[4]=c.x; v[5]=c.y; v[6]=c.z; v[7]=c.w;
    } else {
        #pragma unroll
        for (int i = 0; i < 8; i++) v[i] = 0.f;
    }
    uint4 hi = pack8h(v);
    int slab = k0 >> 6, kin = k0 & 63;
    uint32_t off = swz128((uint32_t)(r * 128 + kin * 2));
    long base = ((long)(b * MT + mt) * NS64 + slab) * AT64 + off;
    *(uint4*)(g_Qh + base) = hi;
}

// Wbig -> SW128 fp16 tile image. thread = (b, nt, r, c8)
__global__ __launch_bounds__(256) void wsplit_k(const float* __restrict__ ans,
                                                const float* __restrict__ Wt)
{
    long idx = (long)blockIdx.x * 256 + threadIdx.x;
    int c8 = (int)(idx % 96);
    long t  = idx / 96;
    int r  = (int)(t % 256);
    t /= 256;
    int nt = (int)(t % NT);
    int b  = (int)(t / NT);
    if (b >= BQ) return;
    int j = nt * 256 + r;
    int k0 = c8 * 8;
    const float* Av = ans + (long)(b * NLYR + 1) * DD + k0;
    float a[8], w1[8], w2[8];
    {
        float4 x = ((const float4*)Av)[0], y = ((const float4*)Av)[1];
        a[0]=x.x; a[1]=x.y; a[2]=x.z; a[3]=x.w; a[4]=y.x; a[5]=y.y; a[6]=y.z; a[7]=y.w;
    }
    if (j < DD) {
        const float* wr = Wt + (long)j * 3 * DD;
        float4 x = *(const float4*)(wr + DD + k0),     y = *(const float4*)(wr + DD + k0 + 4);
        float4 u = *(const float4*)(wr + 2 * DD + k0), w = *(const float4*)(wr + 2 * DD + k0 + 4);
        w1[0]=x.x; w1[1]=x.y; w1[2]=x.z; w1[3]=x.w; w1[4]=y.x; w1[5]=y.y; w1[6]=y.z; w1[7]=y.w;
        w2[0]=u.x; w2[1]=u.y; w2[2]=u.z; w2[3]=u.w; w2[4]=w.x; w2[5]=w.y; w2[6]=w.z; w2[7]=w.w;
    } else {
        int d = j - DD;
        const float* gr = g_G + (long)d * 2 * DD;
        float4 x = *(const float4*)(gr + k0),      y = *(const float4*)(gr + k0 + 4);
        float4 u = *(const float4*)(gr + DD + k0), w = *(const float4*)(gr + DD + k0 + 4);
        w1[0]=x.x; w1[1]=x.y; w1[2]=x.z; w1[3]=x.w; w1[4]=y.x; w1[5]=y.y; w1[6]=y.z; w1[7]=y.w;
        w2[0]=u.x; w2[1]=u.y; w2[2]=u.z; w2[3]=u.w; w2[4]=w.x; w2[5]=w.y; w2[6]=w.z; w2[7]=w.w;
    }
    float v[8];
    #pragma unroll
    for (int i = 0; i < 8; i++) v[i] = w1[i] + w2[i] * a[i];
    uint4 hi = pack8h(v);
    int slab = k0 >> 6, kin = k0 & 63;
    uint32_t off = swz128((uint32_t)(r * 128 + kin * 2));
    long base = ((long)(b * NT + nt) * NS64 + slab) * BT64 + off;
    *(uint4*)(g_Wh + base) = hi;
}

// ---------------- HMMA main GEMM (single-pass fp16) --------------------------
// stage layout: [A 16K][B 32K] = 48KB
__device__ __forceinline__ void copy_slab64(uint32_t sb,
    const unsigned char* qh, const unsigned char* wh, int tid)
{
    int o = tid * 16;   // 256 threads * 16B = 4KB per sweep
    #pragma unroll
    for (int t = 0; t < 4; t++) cpasync16(sb + o + t * 4096,          qh + o + t * 4096);
    #pragma unroll
    for (int t = 0; t < 8; t++) cpasync16(sb + 16384 + o + t * 4096,  wh + o + t * 4096);
    cp_commit();
}

__global__ __launch_bounds__(256, 1)
void tgemm_k(const float* __restrict__ bias, float* __restrict__ Y)
{
    extern __shared__ __align__(1024) unsigned char dsm[];
    uint32_t dbase = smem_u32(dsm);

    int tid  = threadIdx.x;
    int lane = tid & 31;
    int w    = tid >> 5;
    int mw   = w >> 2;        // 0..1 : 64-row block
    int nw   = w & 3;         // 0..3 : 64-col block
    int b    = blockIdx.z;
    int nt   = blockIdx.x;    // 0..5 (256-col tiles)
    int mt   = blockIdx.y;    // 0..46

    const unsigned char* qh = g_Qh + ((long)(b * MT + mt) * NS64) * AT64;
    const unsigned char* wh = g_Wh + ((long)(b * NT + nt) * NS64) * BT64;

    float acc[4][8][4];
    #pragma unroll
    for (int i = 0; i < 4; i++)
        #pragma unroll
        for (int j = 0; j < 8; j++)
            #pragma unroll
            for (int k = 0; k < 4; k++) acc[i][j][k] = 0.f;

    // prologue: stages 0,1,2
    copy_slab64(dbase,             qh,            wh,            tid);
    copy_slab64(dbase + STG64,     qh + AT64,     wh + BT64,     tid);
    copy_slab64(dbase + 2 * STG64, qh + 2 * AT64, wh + 2 * BT64, tid);

    for (int i = 0; i < NS64; i++) {
        asm volatile("cp.async.wait_group 2;" ::: "memory");
        __syncthreads();
        if (i + 3 < NS64) {
            int sl = i + 3;
            copy_slab64(dbase + (uint32_t)((i + 3) & 3) * STG64,
                        qh + (long)sl * AT64, wh + (long)sl * BT64, tid);
        } else {
            cp_commit();   // keep wait_group accounting uniform
        }

        uint32_t sb  = dbase + (uint32_t)(i & 3) * STG64;
        uint32_t a_t = sb, b_t = sb + 16384;

        #pragma unroll
        for (int kk = 0; kk < 64; kk += 16) {
            uint32_t Bh[16];
            #pragma unroll
            for (int g = 0; g < 4; g++)
                ldm_x4(&Bh[g * 4], ldm_addr128(b_t, nw * 64 + g * 16, kk, lane));
            #pragma unroll
            for (int mf = 0; mf < 4; mf++) {
                uint32_t Ah[4];
                ldm_x4(Ah, ldm_addr128(a_t, mw * 64 + mf * 16, kk, lane));
                #pragma unroll
                for (int nf = 0; nf < 8; nf++) {
                    int g = nf >> 1, q = nf & 1;
                    mma16816(acc[mf][nf], Ah, Bh[g * 4 + q], Bh[g * 4 + 2 + q]);
                }
            }
        }
    }

    // ---- epilogue: direct STG with fused bias ----
    long yb = (long)b * NTOT * (2 * DD);
    #pragma unroll
    for (int nf = 0; nf < 8; nf++) {
        int col = nt * 256 + nw * 64 + nf * 8 + (lane & 3) * 2;
        float bv0 = bias[b * 2 * DD + col];
        float bv1 = bias[b * 2 * DD + col + 1];
        #pragma unroll
        for (int mf = 0; mf < 4; mf++) {
            int r0 = mt * 128 + mw * 64 + mf * 16 + (lane >> 2);
            int r1 = r0 + 8;
            float* acp = acc[mf][nf];
            if (r0 < NTOT) {
                float2 v = make_float2(acp[0] + bv0, acp[1] + bv1);
                *(float2*)(Y + yb + (long)r0 * (2 * DD) + col) = v;
            }
            if (r1 < NTOT) {
                float2 v = make_float2(acp[2] + bv0, acp[3] + bv1);
                *(float2*)(Y + yb + (long)r1 * (2 * DD) + col) = v;
            }
        }
    }
}

// ---------------- group max over passages by table id -----------------------
__global__ void tmax_k(const int* __restrict__ tids)
{
    int b   = blockIdx.x / NTOK;
    int tok = blockIdx.x % NTOK;
    int d   = threadIdx.x;
    __shared__ int ids[NP];
    if (threadIdx.x < NP) ids[threadIdx.x] = tids[b * NP + threadIdx.x];
    float m[NTAB];
    #pragma unroll
    for (int t = 0; t < NTAB; t++) m[t] = -3.0e38f;
    __syncthreads();
    const float* Yb = g_Y + (long)b * NTOT * 2 * DD;
    for (int p = 0; p < NP; p++) {
        float v = Yb[(long)(p * NTOK + tok) * 2 * DD + d];
        int id = ids[p];
        #pragma unroll
        for (int t = 0; t < NTAB; t++)
            if (id == t) m[t] = fmaxf(m[t], v);
    }
    #pragma unroll
    for (int t = 0; t < NTAB; t++)
        g_tmax[(((long)b * NTAB + t) * NTOK + tok) * DD + d] = m[t];
}

// ---------------- final -----------------------------------------------------
__global__ void final_k(const float* __restrict__ masks, const int* __restrict__ tids,
                        const float* __restrict__ Wf2, const float* __restrict__ bf2,
                        float* __restrict__ out)
{
    int b = blockIdx.x / NP, p = blockIdx.x % NP;
    int tbl = tids[b * NP + p];
    __shared__ float w2[DD];
    __shared__ float ms[NTOK];
    __shared__ float red[256];
    for (int i = threadIdx.x; i < DD; i += blockDim.x) w2[i] = Wf2[i];
    if (threadIdx.x < NTOK) ms[threadIdx.x] = masks[(b * NP + p) * NTOK + threadIdx.x];
    __syncthreads();

    const float* p1 = g_Y + ((long)b * NTOT + (long)p * NTOK) * 2 * DD + DD;
    const float* p2 = g_p2 + ((long)b * NTAB + tbl) * NTOK * DD;
    float bv = bf2[0];
    float acc = 0.f;
    for (int idx = threadIdx.x; idx < NTOK * DD; idx += blockDim.x) {
        int tok = idx / DD, d = idx % DD;
        float v = p1[(long)tok * 2 * DD + d] + p2[tok * DD + d];
        float s = ms[tok] * w2[d] * fmaxf(v, 0.f);
        if (d == 0) s += bv * ms[tok];
        acc += s;
    }
    red[threadIdx.x] = acc;
    __syncthreads();
    for (int s = 128; s > 0; s >>= 1) {
        if (threadIdx.x < s) red[threadIdx.x] += red[threadIdx.x + s];
        __syncthreads();
    }
    if (threadIdx.x == 0) out[b * NP + p] = red[0];
}

// ---------------- launcher --------------------------------------------------
extern "C" void kernel_launch(void* const* d_in, const int* in_sizes, int n_in,
                              void* d_out, int out_size)
{
    const float* ans   = (const float*)d_in[0];
    const float* qps   = (const float*)d_in[1];
    const float* masks = (const float*)d_in[2];
    const int*   tids  = (const int*)  d_in[3];
    const float* Wp    = (const float*)d_in[4];
    const float* bp    = (const float*)d_in[5];
    const float* Wt    = (const float*)d_in[6];
    const float* bt    = (const float*)d_in[7];
    const float* Wf1   = (const float*)d_in[8];
    const float* bf1   = (const float*)d_in[9];
    const float* Wf2   = (const float*)d_in[10];
    const float* bf2   = (const float*)d_in[11];
    float* out = (float*)d_out;

    void *pG, *pBias, *pY, *pTmax, *pP2;
    cudaGetSymbolAddress(&pG,    g_G);
    cudaGetSymbolAddress(&pBias, g_bias);
    cudaGetSymbolAddress(&pY,    g_Y);
    cudaGetSymbolAddress(&pTmax, g_tmax);
    cudaGetSymbolAddress(&pP2,   g_p2);

    // 1) G = Wf1_p @ [Wp_Q | Wp_AQ]  (B operand n-contiguous -> coalesced path)
    gemm_k<<<dim3(1536 / 128, 768 / 128, 1), 256>>>(
        Wf1, 2 * DD, 0,
        Wp + DD, 1, 3 * DD, 0,
        (const float*)nullptr, 0,
        (float*)pG, 2 * DD, 0,
        DD, 2 * DD, DD);

    // 2) per-batch c_p, c_t ; 3) u
    prep1_k<<<dim3(3, BQ), 256>>>(ans, Wp, bp, Wt, bt);
    prep_u_k<<<dim3(3, BQ), 256>>>(Wf1, bf1);

    // 4) prepack Q and Wbig as SW128 fp16 tile images
    {
        long tq = (long)BQ * MT * 128 * 96;
        qsplit_k<<<(unsigned)((tq + 255) / 256), 256>>>(qps);
        long tw = (long)BQ * NT * 256 * 96;
        wsplit_k<<<(unsigned)((tw + 255) / 256), 256>>>(ans, Wt);
    }

    // 5) main GEMM via mma.sync (single-pass fp16), 4-stage cp.async pipeline
    {
        int dyn = 4 * STG64;   // 192KB
        cudaFuncSetAttribute(tgemm_k, cudaFuncAttributeMaxDynamicSharedMemorySize, dyn);
        tgemm_k<<<dim3(NT, MT, BQ), 256, dyn>>>((const float*)pBias, (float*)pY);
    }

    // 6) table group-max
    tmax_k<<<BQ * NTOK, DD>>>(tids);

    // 7) part2 = tmax @ Wf1_a^T  (B operand k-contiguous -> k-fast path)
    gemm_k<<<dim3(768 / 128, (NTAB * NTOK + 127) / 128, BQ), 256>>>(
        (const float*)pTmax, DD, (long)NTAB * NTOK * DD,
        Wf1 + DD, 2 * DD, 1, 0,
        (const float*)nullptr, 0,
        (float*)pP2, DD, (long)NTAB * NTOK * DD,
        NTAB * NTOK, DD, DD);

    // 8) final masked reduction
    final_k<<<BQ * NP, 256>>>(masks, tids, Wf2, bf2, out);
}

// round 7
// speedup vs baseline: 2.2789x; 1.0037x over previous
#include <cuda_runtime.h>
#include <cuda_fp16.h>
#include <cstdint>

// Problem constants (fixed by setup_inputs)
#define BQ   4
#define NLYR 2
#define NP   100
#define NTOK 60
#define NTOT 6000
#define DD   768
#define NTAB 10

#define MT   47          // m tiles of 128 (6016 >= 6000)
#define NT   6           // n tiles of 256 (1536)
#define NS64 12          // k slabs of 64
#define AT64 16384       // 128 rows x 64 k fp16 = 16KB
#define BT64 32768       // 256 rows x 64 k fp16 = 32KB
#define STG64 49152      // stage: A + B = 48KB

// ---------------- scratch ---------------------------------------------------
__device__ float g_G[DD * 2 * DD];
__device__ float g_cp[BQ * DD];
__device__ float g_bias[BQ * 2 * DD];
__device__ float g_Y[(size_t)BQ * NTOT * 2 * DD];
__device__ float g_tmax[BQ * NTAB * NTOK * DD];
__device__ float g_p2[BQ * NTAB * NTOK * DD];
// pre-swizzled fp16 tile images (SW128, 128B rows, 64-k slabs)
__device__ unsigned char g_Qh[(size_t)BQ * MT * NS64 * AT64];
__device__ unsigned char g_Wh[(size_t)BQ * NT * NS64 * BT64];

// ---------------- PTX helpers ----------------------------------------------
__device__ __forceinline__ uint32_t smem_u32(const void* p) {
    uint32_t a;
    asm("{ .reg .u64 t; cvta.to.shared.u64 t, %1; cvt.u32.u64 %0, t; }" : "=r"(a) : "l"(p));
    return a;
}
__device__ __forceinline__ void cpasync16(uint32_t dst, const void* src) {
    asm volatile("cp.async.cg.shared.global [%0], [%1], 16;" :: "r"(dst), "l"(src));
}
__device__ __forceinline__ void cp_commit() {
    asm volatile("cp.async.commit_group;" ::: "memory");
}
__device__ __forceinline__ void ldm_x4(uint32_t* r, uint32_t addr) {
    asm volatile("ldmatrix.sync.aligned.m8n8.x4.shared.b16 {%0,%1,%2,%3}, [%4];"
                 : "=r"(r[0]), "=r"(r[1]), "=r"(r[2]), "=r"(r[3]) : "r"(addr));
}
__device__ __forceinline__ void mma16816(float* d, const uint32_t* a,
                                         uint32_t b0, uint32_t b1) {
    asm volatile(
        "mma.sync.aligned.m16n8k16.row.col.f32.f16.f16.f32 "
        "{%0,%1,%2,%3}, {%4,%5,%6,%7}, {%8,%9}, {%0,%1,%2,%3};"
        : "+f"(d[0]), "+f"(d[1]), "+f"(d[2]), "+f"(d[3])
        : "r"(a[0]), "r"(a[1]), "r"(a[2]), "r"(a[3]), "r"(b0), "r"(b1));
}
// SW128-swizzled ldmatrix lane address within a (rows x 64k) fp16 tile, 128B rows
__device__ __forceinline__ uint32_t ldm_addr128(uint32_t tilebase, int row0, int k0, int lane) {
    int row = row0 + (lane & 15);
    int kc  = k0 + ((lane >> 4) << 3);
    uint32_t off = (uint32_t)(row * 128 + kc * 2);
    off ^= (off >> 3) & 0x70;
    return tilebase + off;
}
__device__ __forceinline__ uint32_t swz128(uint32_t off) {
    return off ^ ((off >> 3) & 0x70);
}

// ---------------- SIMT GEMM (small ops) -------------------------------------
__global__ __launch_bounds__(256)
void gemm_k(const float* __restrict__ A, long a_rs, long a_bs,
            const float* __restrict__ Bm, long b_ns, long b_ks, long b_bs,
            const float* __restrict__ bias, long bias_bs,
            float* __restrict__ C, long c_ld, long c_bs,
            int M, int N, int K)
{
    const int BM = 128, BN = 128, BK = 16;
    __shared__ float As[BK][BM + 4];
    __shared__ float Bs[BK][BN + 4];
    int bz = blockIdx.z;
    const float* Ab = A  + (long)bz * a_bs;
    const float* Bb = Bm + (long)bz * b_bs;
    float*       Cb = C  + (long)bz * c_bs;
    int m0 = blockIdx.y * BM, n0 = blockIdx.x * BN;
    int tid = threadIdx.x, tx = tid & 15, ty = tid >> 4;
    float acc[8][8];
    #pragma unroll
    for (int i = 0; i < 8; i++)
        #pragma unroll
        for (int j = 0; j < 8; j++) acc[i][j] = 0.f;
    for (int k0 = 0; k0 < K; k0 += BK) {
        #pragma unroll
        for (int i = 0; i < 8; i++) {
            int e = tid + i * 256, m = e >> 4, k = e & 15;
            float v = 0.f;
            if (m0 + m < M) v = Ab[(long)(m0 + m) * a_rs + (k0 + k)];
            As[k][m] = v;
        }
        if (b_ks == 1) {
            #pragma unroll
            for (int i = 0; i < 8; i++) {
                int e = tid + i * 256, n = e >> 4, k = e & 15;
                Bs[k][n] = Bb[(long)(n0 + n) * b_ns + (long)(k0 + k) * b_ks];
            }
        } else {
            #pragma unroll
            for (int i = 0; i < 8; i++) {
                int e = tid + i * 256, k = e >> 7, n = e & 127;
                Bs[k][n] = Bb[(long)(n0 + n) * b_ns + (long)(k0 + k) * b_ks];
            }
        }
        __syncthreads();
        #pragma unroll
        for (int kk = 0; kk < BK; kk++) {
            float a[8], bb[8];
            #pragma unroll
            for (int i = 0; i < 8; i++) a[i]  = As[kk][ty * 8 + i];
            #pragma unroll
            for (int j = 0; j < 8; j++) bb[j] = Bs[kk][tx * 8 + j];
            #pragma unroll
            for (int i = 0; i < 8; i++)
                #pragma unroll
                for (int j = 0; j < 8; j++) acc[i][j] += a[i] * bb[j];
        }
        __syncthreads();
    }
    #pragma unroll
    for (int i = 0; i < 8; i++) {
        int m = m0 + ty * 8 + i;
        if (m < M) {
            #pragma unroll
            for (int j = 0; j < 8; j++) {
                int n = n0 + tx * 8 + j;
                float v = acc[i][j];
                if (bias) v += bias[(long)bz * bias_bs + n];
                Cb[(long)m * c_ld + n] = v;
            }
        }
    }
}

// ---------------- prep kernels ----------------------------------------------
__global__ void prep1_k(const float* __restrict__ ans, const float* __restrict__ Wp,
                        const float* __restrict__ bp, const float* __restrict__ Wt,
                        const float* __restrict__ bt)
{
    int b = blockIdx.y;
    int d = blockIdx.x * blockDim.x + threadIdx.x;
    const float* Av = ans + (long)(b * NLYR + (NLYR - 1)) * DD;
    float sp = bp[d], st = bt[d];
    const float* wpr = Wp + (long)d * 3 * DD;
    const float* wtr = Wt + (long)d * 3 * DD;
    for (int k = 0; k < DD; k++) {
        float a = Av[k];
        sp += wpr[k] * a;
        st += wtr[k] * a;
    }
    g_cp[b * DD + d] = sp;
    g_bias[b * 2 * DD + d] = st;
}

__global__ void prep_u_k(const float* __restrict__ Wf1, const float* __restrict__ bf1)
{
    int b = blockIdx.y;
    int d = blockIdx.x * blockDim.x + threadIdx.x;
    const float* cp = g_cp + b * DD;
    const float* wr = Wf1 + (long)d * 2 * DD;
    float s = bf1[d];
    for (int k = 0; k < DD; k++) s += wr[k] * cp[k];
    g_bias[b * 2 * DD + DD + d] = s;
}

// ---------------- fp16 pack helper ------------------------------------------
__device__ __forceinline__ uint4 pack8h(const float* v) {
    unsigned short h[8];
    #pragma unroll
    for (int i = 0; i < 8; i++) h[i] = __half_as_ushort(__float2half_rn(v[i]));
    uint4 r;
    r.x = h[0] | ((uint32_t)h[1] << 16); r.y = h[2] | ((uint32_t)h[3] << 16);
    r.z = h[4] | ((uint32_t)h[5] << 16); r.w = h[6] | ((uint32_t)h[7] << 16);
    return r;
}

// Q -> SW128 fp16 tile image. thread = (b, mt, r, c8)
__global__ __launch_bounds__(256) void qsplit_k(const float* __restrict__ qps)
{
    long idx = (long)blockIdx.x * 256 + threadIdx.x;
    int c8 = (int)(idx % 96);
    long t  = idx / 96;
    int r  = (int)(t % 128);
    t /= 128;
    int mt = (int)(t % MT);
    int b  = (int)(t / MT);
    if (b >= BQ) return;
    int m = mt * 128 + r;
    int k0 = c8 * 8;
    float v[8];
    if (m < NTOT) {
        const float* src = qps + ((long)(b * NLYR + 1) * NTOT + m) * DD + k0;
        float4 a = ((const float4*)src)[0];
        float4 c = ((const float4*)src)[1];
        v[0]=a.x; v[1]=a.y; v[2]=a.z; v[3]=a.w; v[4]=c.x; v[5]=c.y; v[6]=c.z; v[7]=c.w;
    } else {
        #pragma unroll
        for (int i = 0; i < 8; i++) v[i] = 0.f;
    }
    uint4 hi = pack8h(v);
    int slab = k0 >> 6, kin = k0 & 63;
    uint32_t off = swz128((uint32_t)(r * 128 + kin * 2));
    long base = ((long)(b * MT + mt) * NS64 + slab) * AT64 + off;
    *(uint4*)(g_Qh + base) = hi;
}

// Wbig -> SW128 fp16 tile image. thread = (b, nt, r, c8)
__global__ __launch_bounds__(256) void wsplit_k(const float* __restrict__ ans,
                                                const float* __restrict__ Wt)
{
    long idx = (long)blockIdx.x * 256 + threadIdx.x;
    int c8 = (int)(idx % 96);
    long t  = idx / 96;
    int r  = (int)(t % 256);
    t /= 256;
    int nt = (int)(t % NT);
    int b  = (int)(t / NT);
    if (b >= BQ) return;
    int j = nt * 256 + r;
    int k0 = c8 * 8;
    const float* Av = ans + (long)(b * NLYR + 1) * DD + k0;
    float a[8], w1[8], w2[8];
    {
        float4 x = ((const float4*)Av)[0], y = ((const float4*)Av)[1];
        a[0]=x.x; a[1]=x.y; a[2]=x.z; a[3]=x.w; a[4]=y.x; a[5]=y.y; a[6]=y.z; a[7]=y.w;
    }
    if (j < DD) {
        const float* wr = Wt + (long)j * 3 * DD;
        float4 x = *(const float4*)(wr + DD + k0),     y = *(const float4*)(wr + DD + k0 + 4);
        float4 u = *(const float4*)(wr + 2 * DD + k0), w = *(const float4*)(wr + 2 * DD + k0 + 4);
        w1[0]=x.x; w1[1]=x.y; w1[2]=x.z; w1[3]=x.w; w1[4]=y.x; w1[5]=y.y; w1[6]=y.z; w1[7]=y.w;
        w2[0]=u.x; w2[1]=u.y; w2[2]=u.z; w2[3]=u.w; w2[4]=w.x; w2[5]=w.y; w2[6]=w.z; w2[7]=w.w;
    } else {
        int d = j - DD;
        const float* gr = g_G + (long)d * 2 * DD;
        float4 x = *(const float4*)(gr + k0),      y = *(const float4*)(gr + k0 + 4);
        float4 u = *(const float4*)(gr + DD + k0), w = *(const float4*)(gr + DD + k0 + 4);
        w1[0]=x.x; w1[1]=x.y; w1[2]=x.z; w1[3]=x.w; w1[4]=y.x; w1[5]=y.y; w1[6]=y.z; w1[7]=y.w;
        w2[0]=u.x; w2[1]=u.y; w2[2]=u.z; w2[3]=u.w; w2[4]=w.x; w2[5]=w.y; w2[6]=w.z; w2[7]=w.w;
    }
    float v[8];
    #pragma unroll
    for (int i = 0; i < 8; i++) v[i] = w1[i] + w2[i] * a[i];
    uint4 hi = pack8h(v);
    int slab = k0 >> 6, kin = k0 & 63;
    uint32_t off = swz128((uint32_t)(r * 128 + kin * 2));
    long base = ((long)(b * NT + nt) * NS64 + slab) * BT64 + off;
    *(uint4*)(g_Wh + base) = hi;
}

// ---------------- HMMA main GEMM (single-pass fp16, 512 threads) -------------
// stage layout: [A 16K][B 32K] = 48KB
__device__ __forceinline__ void copy_slab64(uint32_t sb,
    const unsigned char* qh, const unsigned char* wh, int tid)
{
    int o = tid * 16;   // 512 threads * 16B = 8KB per sweep
    #pragma unroll
    for (int t = 0; t < 2; t++) cpasync16(sb + o + t * 8192,          qh + o + t * 8192);
    #pragma unroll
    for (int t = 0; t < 4; t++) cpasync16(sb + 16384 + o + t * 8192,  wh + o + t * 8192);
    cp_commit();
}

__global__ __launch_bounds__(512, 1)
void tgemm_k(const float* __restrict__ bias, float* __restrict__ Y)
{
    extern __shared__ __align__(1024) unsigned char dsm[];
    uint32_t dbase = smem_u32(dsm);

    int tid  = threadIdx.x;
    int lane = tid & 31;
    int w    = tid >> 5;      // 0..15
    int mw   = w & 1;         // 0..1 : 64-row block
    int nw   = w >> 1;        // 0..7 : 32-col block
    int b    = blockIdx.z;
    int nt   = blockIdx.x;    // 0..5 (256-col tiles)
    int mt   = blockIdx.y;    // 0..46

    const unsigned char* qh = g_Qh + ((long)(b * MT + mt) * NS64) * AT64;
    const unsigned char* wh = g_Wh + ((long)(b * NT + nt) * NS64) * BT64;

    float acc[4][4][4];
    #pragma unroll
    for (int i = 0; i < 4; i++)
        #pragma unroll
        for (int j = 0; j < 4; j++)
            #pragma unroll
            for (int k = 0; k < 4; k++) acc[i][j][k] = 0.f;

    // prologue: stages 0,1,2
    copy_slab64(dbase,             qh,            wh,            tid);
    copy_slab64(dbase + STG64,     qh + AT64,     wh + BT64,     tid);
    copy_slab64(dbase + 2 * STG64, qh + 2 * AT64, wh + 2 * BT64, tid);

    for (int i = 0; i < NS64; i++) {
        asm volatile("cp.async.wait_group 2;" ::: "memory");
        __syncthreads();
        if (i + 3 < NS64) {
            int sl = i + 3;
            copy_slab64(dbase + (uint32_t)((i + 3) & 3) * STG64,
                        qh + (long)sl * AT64, wh + (long)sl * BT64, tid);
        } else {
            cp_commit();   // keep wait_group accounting uniform
        }

        uint32_t sb  = dbase + (uint32_t)(i & 3) * STG64;
        uint32_t a_t = sb, b_t = sb + 16384;

        #pragma unroll
        for (int kk = 0; kk < 64; kk += 16) {
            uint32_t Bh[8];
            #pragma unroll
            for (int g = 0; g < 2; g++)
                ldm_x4(&Bh[g * 4], ldm_addr128(b_t, nw * 32 + g * 16, kk, lane));
            #pragma unroll
            for (int mf = 0; mf < 4; mf++) {
                uint32_t Ah[4];
                ldm_x4(Ah, ldm_addr128(a_t, mw * 64 + mf * 16, kk, lane));
                #pragma unroll
                for (int nf = 0; nf < 4; nf++) {
                    int g = nf >> 1, q = nf & 1;
                    mma16816(acc[mf][nf], Ah, Bh[g * 4 + q], Bh[g * 4 + 2 + q]);
                }
            }
        }
    }

    // ---- epilogue: direct STG with fused bias ----
    long yb = (long)b * NTOT * (2 * DD);
    #pragma unroll
    for (int nf = 0; nf < 4; nf++) {
        int col = nt * 256 + nw * 32 + nf * 8 + (lane & 3) * 2;
        float bv0 = bias[b * 2 * DD + col];
        float bv1 = bias[b * 2 * DD + col + 1];
        #pragma unroll
        for (int mf = 0; mf < 4; mf++) {
            int r0 = mt * 128 + mw * 64 + mf * 16 + (lane >> 2);
            int r1 = r0 + 8;
            float* acp = acc[mf][nf];
            if (r0 < NTOT) {
                float2 v = make_float2(acp[0] + bv0, acp[1] + bv1);
                *(float2*)(Y + yb + (long)r0 * (2 * DD) + col) = v;
            }
            if (r1 < NTOT) {
                float2 v = make_float2(acp[2] + bv0, acp[3] + bv1);
                *(float2*)(Y + yb + (long)r1 * (2 * DD) + col) = v;
            }
        }
    }
}

// ---------------- group max over passages by table id -----------------------
__global__ void tmax_k(const int* __restrict__ tids)
{
    int b   = blockIdx.x / NTOK;
    int tok = blockIdx.x % NTOK;
    int d   = threadIdx.x;
    __shared__ int ids[NP];
    if (threadIdx.x < NP) ids[threadIdx.x] = tids[b * NP + threadIdx.x];
    float m[NTAB];
    #pragma unroll
    for (int t = 0; t < NTAB; t++) m[t] = -3.0e38f;
    __syncthreads();
    const float* Yb = g_Y + (long)b * NTOT * 2 * DD;
    for (int p = 0; p < NP; p++) {
        float v = Yb[(long)(p * NTOK + tok) * 2 * DD + d];
        int id = ids[p];
        #pragma unroll
        for (int t = 0; t < NTAB; t++)
            if (id == t) m[t] = fmaxf(m[t], v);
    }
    #pragma unroll
    for (int t = 0; t < NTAB; t++)
        g_tmax[(((long)b * NTAB + t) * NTOK + tok) * DD + d] = m[t];
}

// ---------------- final -----------------------------------------------------
__global__ void final_k(const float* __restrict__ masks, const int* __restrict__ tids,
                        const float* __restrict__ Wf2, const float* __restrict__ bf2,
                        float* __restrict__ out)
{
    int b = blockIdx.x / NP, p = blockIdx.x % NP;
    int tbl = tids[b * NP + p];
    __shared__ float w2[DD];
    __shared__ float ms[NTOK];
    __shared__ float red[256];
    for (int i = threadIdx.x; i < DD; i += blockDim.x) w2[i] = Wf2[i];
    if (threadIdx.x < NTOK) ms[threadIdx.x] = masks[(b * NP + p) * NTOK + threadIdx.x];
    __syncthreads();

    const float* p1 = g_Y + ((long)b * NTOT + (long)p * NTOK) * 2 * DD + DD;
    const float* p2 = g_p2 + ((long)b * NTAB + tbl) * NTOK * DD;
    float bv = bf2[0];
    float acc = 0.f;
    for (int idx = threadIdx.x; idx < NTOK * DD; idx += blockDim.x) {
        int tok = idx / DD, d = idx % DD;
        float v = p1[(long)tok * 2 * DD + d] + p2[tok * DD + d];
        float s = ms[tok] * w2[d] * fmaxf(v, 0.f);
        if (d == 0) s += bv * ms[tok];
        acc += s;
    }
    red[threadIdx.x] = acc;
    __syncthreads();
    for (int s = 128; s > 0; s >>= 1) {
        if (threadIdx.x < s) red[threadIdx.x] += red[threadIdx.x + s];
        __syncthreads();
    }
    if (threadIdx.x == 0) out[b * NP + p] = red[0];
}

// ---------------- launcher --------------------------------------------------
extern "C" void kernel_launch(void* const* d_in, const int* in_sizes, int n_in,
                              void* d_out, int out_size)
{
    const float* ans   = (const float*)d_in[0];
    const float* qps   = (const float*)d_in[1];
    const float* masks = (const float*)d_in[2];
    const int*   tids  = (const int*)  d_in[3];
    const float* Wp    = (const float*)d_in[4];
    const float* bp    = (const float*)d_in[5];
    const float* Wt    = (const float*)d_in[6];
    const float* bt    = (const float*)d_in[7];
    const float* Wf1   = (const float*)d_in[8];
    const float* bf1   = (const float*)d_in[9];
    const float* Wf2   = (const float*)d_in[10];
    const float* bf2   = (const float*)d_in[11];
    float* out = (float*)d_out;

    void *pG, *pBias, *pY, *pTmax, *pP2;
    cudaGetSymbolAddress(&pG,    g_G);
    cudaGetSymbolAddress(&pBias, g_bias);
    cudaGetSymbolAddress(&pY,    g_Y);
    cudaGetSymbolAddress(&pTmax, g_tmax);
    cudaGetSymbolAddress(&pP2,   g_p2);

    // 1) G = Wf1_p @ [Wp_Q | Wp_AQ]
    gemm_k<<<dim3(1536 / 128, 768 / 128, 1), 256>>>(
        Wf1, 2 * DD, 0,
        Wp + DD, 1, 3 * DD, 0,
        (const float*)nullptr, 0,
        (float*)pG, 2 * DD, 0,
        DD, 2 * DD, DD);

    // 2) per-batch c_p, c_t ; 3) u
    prep1_k<<<dim3(3, BQ), 256>>>(ans, Wp, bp, Wt, bt);
    prep_u_k<<<dim3(3, BQ), 256>>>(Wf1, bf1);

    // 4) prepack Q and Wbig as SW128 fp16 tile images
    {
        long tq = (long)BQ * MT * 128 * 96;
        qsplit_k<<<(unsigned)((tq + 255) / 256), 256>>>(qps);
        long tw = (long)BQ * NT * 256 * 96;
        wsplit_k<<<(unsigned)((tw + 255) / 256), 256>>>(ans, Wt);
    }

    // 5) main GEMM via mma.sync (single-pass fp16), 512 threads, 4-stage pipeline
    {
        int dyn = 4 * STG64;   // 192KB
        cudaFuncSetAttribute(tgemm_k, cudaFuncAttributeMaxDynamicSharedMemorySize, dyn);
        tgemm_k<<<dim3(NT, MT, BQ), 512, dyn>>>((const float*)pBias, (float*)pY);
    }

    // 6) table group-max
    tmax_k<<<BQ * NTOK, DD>>>(tids);

    // 7) part2 = tmax @ Wf1_a^T
    gemm_k<<<dim3(768 / 128, (NTAB * NTOK + 127) / 128, BQ), 256>>>(
        (const float*)pTmax, DD, (long)NTAB * NTOK * DD,
        Wf1 + DD, 2 * DD, 1, 0,
        (const float*)nullptr, 0,
        (float*)pP2, DD, (long)NTAB * NTOK * DD,
        NTAB * NTOK, DD, DD);

    // 8) final masked reduction
    final_k<<<BQ * NP, 256>>>(masks, tids, Wf2, bf2, out);
}

// round 8
// speedup vs baseline: 2.2846x; 1.0025x over previous
#include <cuda_runtime.h>
#include <cuda_fp16.h>
#include <cstdint>

// Problem constants (fixed by setup_inputs)
#define BQ   4
#define NLYR 2
#define NP   100
#define NTOK 60
#define NTOT 6000
#define DD   768
#define NTAB 10

#define MT   47          // m tiles of 128 (6016 >= 6000)
#define NT   6           // n tiles of 256 (1536)
#define NS64 12          // k slabs of 64
#define AT64 16384       // 128 rows x 64 k fp16 = 16KB
#define BT64 32768       // 256 rows x 64 k fp16 = 32KB
#define STG64 49152      // stage: A + B = 48KB

// ---------------- scratch ---------------------------------------------------
__device__ float g_G[DD * 2 * DD];
__device__ float g_cp[BQ * DD];
__device__ float g_bias[BQ * 2 * DD];
__device__ float g_Y[(size_t)BQ * NTOT * 2 * DD];
__device__ float g_tmax[BQ * NTAB * NTOK * DD];
__device__ float g_p2[BQ * NTAB * NTOK * DD];
// pre-swizzled fp16 tile images (SW128, 128B rows, 64-k slabs)
__device__ unsigned char g_Qh[(size_t)BQ * MT * NS64 * AT64];
__device__ unsigned char g_Wh[(size_t)BQ * NT * NS64 * BT64];

// ---------------- PTX helpers ----------------------------------------------
__device__ __forceinline__ uint32_t smem_u32(const void* p) {
    uint32_t a;
    asm("{ .reg .u64 t; cvta.to.shared.u64 t, %1; cvt.u32.u64 %0, t; }" : "=r"(a) : "l"(p));
    return a;
}
__device__ __forceinline__ void ldm_x4(uint32_t* r, uint32_t addr) {
    asm volatile("ldmatrix.sync.aligned.m8n8.x4.shared.b16 {%0,%1,%2,%3}, [%4];"
                 : "=r"(r[0]), "=r"(r[1]), "=r"(r[2]), "=r"(r[3]) : "r"(addr));
}
__device__ __forceinline__ void mma16816(float* d, const uint32_t* a,
                                         uint32_t b0, uint32_t b1) {
    asm volatile(
        "mma.sync.aligned.m16n8k16.row.col.f32.f16.f16.f32 "
        "{%0,%1,%2,%3}, {%4,%5,%6,%7}, {%8,%9}, {%0,%1,%2,%3};"
        : "+f"(d[0]), "+f"(d[1]), "+f"(d[2]), "+f"(d[3])
        : "r"(a[0]), "r"(a[1]), "r"(a[2]), "r"(a[3]), "r"(b0), "r"(b1));
}
// SW128-swizzled ldmatrix lane address within a (rows x 64k) fp16 tile, 128B rows
__device__ __forceinline__ uint32_t ldm_addr128(uint32_t tilebase, int row0, int k0, int lane) {
    int row = row0 + (lane & 15);
    int kc  = k0 + ((lane >> 4) << 3);
    uint32_t off = (uint32_t)(row * 128 + kc * 2);
    off ^= (off >> 3) & 0x70;
    return tilebase + off;
}
__device__ __forceinline__ uint32_t swz128(uint32_t off) {
    return off ^ ((off >> 3) & 0x70);
}
// ---- bulk-copy (TMA engine, non-tensor) + mbarrier ----
__device__ __forceinline__ void mbar_init(uint32_t mb, uint32_t cnt) {
    asm volatile("mbarrier.init.shared.b64 [%0], %1;" :: "r"(mb), "r"(cnt) : "memory");
}
__device__ __forceinline__ void mbar_expect(uint32_t mb, uint32_t bytes) {
    asm volatile("mbarrier.arrive.expect_tx.shared.b64 _, [%0], %1;"
                 :: "r"(mb), "r"(bytes) : "memory");
}
__device__ __forceinline__ void bulkcp(uint32_t dst, const void* src, uint32_t bytes, uint32_t mb) {
    asm volatile("cp.async.bulk.shared::cluster.global.mbarrier::complete_tx::bytes "
                 "[%0], [%1], %2, [%3];"
                 :: "r"(dst), "l"(src), "r"(bytes), "r"(mb) : "memory");
}
__device__ __forceinline__ void mbar_wait(uint32_t mb, uint32_t parity) {
    asm volatile(
        "{\n\t.reg .pred P1;\n\t"
        "WAITLP_%=:\n\t"
        "mbarrier.try_wait.parity.acquire.cta.shared::cta.b64 P1, [%0], %1, 0x989680;\n\t"
        "@P1 bra.uni WAITDN_%=;\n\t"
        "bra.uni WAITLP_%=;\n\t"
        "WAITDN_%=:\n\t}"
        :: "r"(mb), "r"(parity) : "memory");
}

// ---------------- SIMT GEMM (small ops) -------------------------------------
__global__ __launch_bounds__(256)
void gemm_k(const float* __restrict__ A, long a_rs, long a_bs,
            const float* __restrict__ Bm, long b_ns, long b_ks, long b_bs,
            const float* __restrict__ bias, long bias_bs,
            float* __restrict__ C, long c_ld, long c_bs,
            int M, int N, int K)
{
    const int BM = 128, BN = 128, BK = 16;
    __shared__ float As[BK][BM + 4];
    __shared__ float Bs[BK][BN + 4];
    int bz = blockIdx.z;
    const float* Ab = A  + (long)bz * a_bs;
    const float* Bb = Bm + (long)bz * b_bs;
    float*       Cb = C  + (long)bz * c_bs;
    int m0 = blockIdx.y * BM, n0 = blockIdx.x * BN;
    int tid = threadIdx.x, tx = tid & 15, ty = tid >> 4;
    float acc[8][8];
    #pragma unroll
    for (int i = 0; i < 8; i++)
        #pragma unroll
        for (int j = 0; j < 8; j++) acc[i][j] = 0.f;
    for (int k0 = 0; k0 < K; k0 += BK) {
        #pragma unroll
        for (int i = 0; i < 8; i++) {
            int e = tid + i * 256, m = e >> 4, k = e & 15;
            float v = 0.f;
            if (m0 + m < M) v = Ab[(long)(m0 + m) * a_rs + (k0 + k)];
            As[k][m] = v;
        }
        if (b_ks == 1) {
            #pragma unroll
            for (int i = 0; i < 8; i++) {
                int e = tid + i * 256, n = e >> 4, k = e & 15;
                Bs[k][n] = Bb[(long)(n0 + n) * b_ns + (long)(k0 + k) * b_ks];
            }
        } else {
            #pragma unroll
            for (int i = 0; i < 8; i++) {
                int e = tid + i * 256, k = e >> 7, n = e & 127;
                Bs[k][n] = Bb[(long)(n0 + n) * b_ns + (long)(k0 + k) * b_ks];
            }
        }
        __syncthreads();
        #pragma unroll
        for (int kk = 0; kk < BK; kk++) {
            float a[8], bb[8];
            #pragma unroll
            for (int i = 0; i < 8; i++) a[i]  = As[kk][ty * 8 + i];
            #pragma unroll
            for (int j = 0; j < 8; j++) bb[j] = Bs[kk][tx * 8 + j];
            #pragma unroll
            for (int i = 0; i < 8; i++)
                #pragma unroll
                for (int j = 0; j < 8; j++) acc[i][j] += a[i] * bb[j];
        }
        __syncthreads();
    }
    #pragma unroll
    for (int i = 0; i < 8; i++) {
        int m = m0 + ty * 8 + i;
        if (m < M) {
            #pragma unroll
            for (int j = 0; j < 8; j++) {
                int n = n0 + tx * 8 + j;
                float v = acc[i][j];
                if (bias) v += bias[(long)bz * bias_bs + n];
                Cb[(long)m * c_ld + n] = v;
            }
        }
    }
}

// ---------------- prep kernels ----------------------------------------------
__global__ void prep1_k(const float* __restrict__ ans, const float* __restrict__ Wp,
                        const float* __restrict__ bp, const float* __restrict__ Wt,
                        const float* __restrict__ bt)
{
    int b = blockIdx.y;
    int d = blockIdx.x * blockDim.x + threadIdx.x;
    const float* Av = ans + (long)(b * NLYR + (NLYR - 1)) * DD;
    float sp = bp[d], st = bt[d];
    const float* wpr = Wp + (long)d * 3 * DD;
    const float* wtr = Wt + (long)d * 3 * DD;
    for (int k = 0; k < DD; k++) {
        float a = Av[k];
        sp += wpr[k] * a;
        st += wtr[k] * a;
    }
    g_cp[b * DD + d] = sp;
    g_bias[b * 2 * DD + d] = st;
}

__global__ void prep_u_k(const float* __restrict__ Wf1, const float* __restrict__ bf1)
{
    int b = blockIdx.y;
    int d = blockIdx.x * blockDim.x + threadIdx.x;
    const float* cp = g_cp + b * DD;
    const float* wr = Wf1 + (long)d * 2 * DD;
    float s = bf1[d];
    for (int k = 0; k < DD; k++) s += wr[k] * cp[k];
    g_bias[b * 2 * DD + DD + d] = s;
}

// ---------------- fp16 pack helper ------------------------------------------
__device__ __forceinline__ uint4 pack8h(const float* v) {
    unsigned short h[8];
    #pragma unroll
    for (int i = 0; i < 8; i++) h[i] = __half_as_ushort(__float2half_rn(v[i]));
    uint4 r;
    r.x = h[0] | ((uint32_t)h[1] << 16); r.y = h[2] | ((uint32_t)h[3] << 16);
    r.z = h[4] | ((uint32_t)h[5] << 16); r.w = h[6] | ((uint32_t)h[7] << 16);
    return r;
}

// Q -> SW128 fp16 tile image. thread = (b, mt, r, c8)
__global__ __launch_bounds__(256) void qsplit_k(const float* __restrict__ qps)
{
    long idx = (long)blockIdx.x * 256 + threadIdx.x;
    int c8 = (int)(idx % 96);
    long t  = idx / 96;
    int r  = (int)(t % 128);
    t /= 128;
    int mt = (int)(t % MT);
    int b  = (int)(t / MT);
    if (b >= BQ) return;
    int m = mt * 128 + r;
    int k0 = c8 * 8;
    float v[8];
    if (m < NTOT) {
        const float* src = qps + ((long)(b * NLYR + 1) * NTOT + m) * DD + k0;
        float4 a = ((const float4*)src)[0];
        float4 c = ((const float4*)src)[1];
        v[0]=a.x; v[1]=a.y; v[2]=a.z; v[3]=a.w; v[4]=c.x; v[5]=c.y; v[6]=c.z; v[7]=c.w;
    } else {
        #pragma unroll
        for (int i = 0; i < 8; i++) v[i] = 0.f;
    }
    uint4 hi = pack8h(v);
    int slab = k0 >> 6, kin = k0 & 63;
    uint32_t off = swz128((uint32_t)(r * 128 + kin * 2));
    long base = ((long)(b * MT + mt) * NS64 + slab) * AT64 + off;
    *(uint4*)(g_Qh + base) = hi;
}

// Wbig -> SW128 fp16 tile image. thread = (b, nt, r, c8)
__global__ __launch_bounds__(256) void wsplit_k(const float* __restrict__ ans,
                                                const float* __restrict__ Wt)
{
    long idx = (long)blockIdx.x * 256 + threadIdx.x;
    int c8 = (int)(idx % 96);
    long t  = idx / 96;
    int r  = (int)(t % 256);
    t /= 256;
    int nt = (int)(t % NT);
    int b  = (int)(t / NT);
    if (b >= BQ) return;
    int j = nt * 256 + r;
    int k0 = c8 * 8;
    const float* Av = ans + (long)(b * NLYR + 1) * DD + k0;
    float a[8], w1[8], w2[8];
    {
        float4 x = ((const float4*)Av)[0], y = ((const float4*)Av)[1];
        a[0]=x.x; a[1]=x.y; a[2]=x.z; a[3]=x.w; a[4]=y.x; a[5]=y.y; a[6]=y.z; a[7]=y.w;
    }
    if (j < DD) {
        const float* wr = Wt + (long)j * 3 * DD;
        float4 x = *(const float4*)(wr + DD + k0),     y = *(const float4*)(wr + DD + k0 + 4);
        float4 u = *(const float4*)(wr + 2 * DD + k0), w = *(const float4*)(wr + 2 * DD + k0 + 4);
        w1[0]=x.x; w1[1]=x.y; w1[2]=x.z; w1[3]=x.w; w1[4]=y.x; w1[5]=y.y; w1[6]=y.z; w1[7]=y.w;
        w2[0]=u.x; w2[1]=u.y; w2[2]=u.z; w2[3]=u.w; w2[4]=w.x; w2[5]=w.y; w2[6]=w.z; w2[7]=w.w;
    } else {
        int d = j - DD;
        const float* gr = g_G + (long)d * 2 * DD;
        float4 x = *(const float4*)(gr + k0),      y = *(const float4*)(gr + k0 + 4);
        float4 u = *(const float4*)(gr + DD + k0), w = *(const float4*)(gr + DD + k0 + 4);
        w1[0]=x.x; w1[1]=x.y; w1[2]=x.z; w1[3]=x.w; w1[4]=y.x; w1[5]=y.y; w1[6]=y.z; w1[7]=y.w;
        w2[0]=u.x; w2[1]=u.y; w2[2]=u.z; w2[3]=u.w; w2[4]=w.x; w2[5]=w.y; w2[6]=w.z; w2[7]=w.w;
    }
    float v[8];
    #pragma unroll
    for (int i = 0; i < 8; i++) v[i] = w1[i] + w2[i] * a[i];
    uint4 hi = pack8h(v);
    int slab = k0 >> 6, kin = k0 & 63;
    uint32_t off = swz128((uint32_t)(r * 128 + kin * 2));
    long base = ((long)(b * NT + nt) * NS64 + slab) * BT64 + off;
    *(uint4*)(g_Wh + base) = hi;
}

// ---------------- HMMA main GEMM (fp16, bulk-copy pipeline) ------------------
// stage layout: [A 16K][B 32K] = 48KB; 4-stage mbarrier ring
__global__ __launch_bounds__(512, 1)
void tgemm_k(const float* __restrict__ bias, float* __restrict__ Y)
{
    extern __shared__ __align__(1024) unsigned char dsm[];
    __shared__ __align__(8) uint64_t s_mbar[4];
    uint32_t dbase = smem_u32(dsm);
    uint32_t mb0   = smem_u32(&s_mbar[0]);

    int tid  = threadIdx.x;
    int lane = tid & 31;
    int w    = tid >> 5;      // 0..15
    int mw   = w & 1;         // 0..1 : 64-row block
    int nw   = w >> 1;        // 0..7 : 32-col block
    int b    = blockIdx.z;
    int nt   = blockIdx.x;    // 0..5 (256-col tiles)
    int mt   = blockIdx.y;    // 0..46

    const unsigned char* qh = g_Qh + ((long)(b * MT + mt) * NS64) * AT64;
    const unsigned char* wh = g_Wh + ((long)(b * NT + nt) * NS64) * BT64;

    float acc[4][4][4];
    #pragma unroll
    for (int i = 0; i < 4; i++)
        #pragma unroll
        for (int j = 0; j < 4; j++)
            #pragma unroll
            for (int k = 0; k < 4; k++) acc[i][j][k] = 0.f;

    if (tid == 0) {
        #pragma unroll
        for (int s = 0; s < 4; s++) mbar_init(mb0 + s * 8, 1);
    }
    asm volatile("fence.proxy.async.shared::cta;" ::: "memory");
    __syncthreads();

    // prologue: issue stages 0,1,2 via TMA-engine bulk copies
    if (tid == 0) {
        #pragma unroll
        for (int s = 0; s < 3; s++) {
            uint32_t mb = mb0 + s * 8;
            uint32_t sb = dbase + (uint32_t)s * STG64;
            mbar_expect(mb, STG64);
            bulkcp(sb,          qh + (long)s * AT64, AT64, mb);
            bulkcp(sb + AT64,   wh + (long)s * BT64, BT64, mb);
        }
    }

    for (int i = 0; i < NS64; i++) {
        int s = i & 3;
        mbar_wait(mb0 + s * 8, (i >> 2) & 1);
        __syncthreads();   // all warps done with iter i-1 (stage (i+3)&3 free)
        if (tid == 0 && i + 3 < NS64) {
            int sl = i + 3, ss = sl & 3;
            uint32_t mb = mb0 + ss * 8;
            uint32_t sbw = dbase + (uint32_t)ss * STG64;
            mbar_expect(mb, STG64);
            bulkcp(sbw,        qh + (long)sl * AT64, AT64, mb);
            bulkcp(sbw + AT64, wh + (long)sl * BT64, BT64, mb);
        }

        uint32_t sb  = dbase + (uint32_t)s * STG64;
        uint32_t a_t = sb, b_t = sb + 16384;

        #pragma unroll
        for (int kk = 0; kk < 64; kk += 16) {
            uint32_t Bh[8];
            #pragma unroll
            for (int g = 0; g < 2; g++)
                ldm_x4(&Bh[g * 4], ldm_addr128(b_t, nw * 32 + g * 16, kk, lane));
            #pragma unroll
            for (int mf = 0; mf < 4; mf++) {
                uint32_t Ah[4];
                ldm_x4(Ah, ldm_addr128(a_t, mw * 64 + mf * 16, kk, lane));
                #pragma unroll
                for (int nf = 0; nf < 4; nf++) {
                    int g = nf >> 1, q = nf & 1;
                    mma16816(acc[mf][nf], Ah, Bh[g * 4 + q], Bh[g * 4 + 2 + q]);
                }
            }
        }
    }

    // ---- epilogue: direct STG with fused bias ----
    long yb = (long)b * NTOT * (2 * DD);
    #pragma unroll
    for (int nf = 0; nf < 4; nf++) {
        int col = nt * 256 + nw * 32 + nf * 8 + (lane & 3) * 2;
        float bv0 = bias[b * 2 * DD + col];
        float bv1 = bias[b * 2 * DD + col + 1];
        #pragma unroll
        for (int mf = 0; mf < 4; mf++) {
            int r0 = mt * 128 + mw * 64 + mf * 16 + (lane >> 2);
            int r1 = r0 + 8;
            float* acp = acc[mf][nf];
            if (r0 < NTOT) {
                float2 v = make_float2(acp[0] + bv0, acp[1] + bv1);
                *(float2*)(Y + yb + (long)r0 * (2 * DD) + col) = v;
            }
            if (r1 < NTOT) {
                float2 v = make_float2(acp[2] + bv0, acp[3] + bv1);
                *(float2*)(Y + yb + (long)r1 * (2 * DD) + col) = v;
            }
        }
    }
}

// ---------------- group max over passages by table id -----------------------
__global__ void tmax_k(const int* __restrict__ tids)
{
    int b   = blockIdx.x / NTOK;
    int tok = blockIdx.x % NTOK;
    int d   = threadIdx.x;
    __shared__ int ids[NP];
    if (threadIdx.x < NP) ids[threadIdx.x] = tids[b * NP + threadIdx.x];
    float m[NTAB];
    #pragma unroll
    for (int t = 0; t < NTAB; t++) m[t] = -3.0e38f;
    __syncthreads();
    const float* Yb = g_Y + (long)b * NTOT * 2 * DD;
    for (int p = 0; p < NP; p++) {
        float v = Yb[(long)(p * NTOK + tok) * 2 * DD + d];
        int id = ids[p];
        #pragma unroll
        for (int t = 0; t < NTAB; t++)
            if (id == t) m[t] = fmaxf(m[t], v);
    }
    #pragma unroll
    for (int t = 0; t < NTAB; t++)
        g_tmax[(((long)b * NTAB + t) * NTOK + tok) * DD + d] = m[t];
}

// ---------------- final -----------------------------------------------------
__global__ void final_k(const float* __restrict__ masks, const int* __restrict__ tids,
                        const float* __restrict__ Wf2, const float* __restrict__ bf2,
                        float* __restrict__ out)
{
    int b = blockIdx.x / NP, p = blockIdx.x % NP;
    int tbl = tids[b * NP + p];
    __shared__ float w2[DD];
    __shared__ float ms[NTOK];
    __shared__ float red[256];
    for (int i = threadIdx.x; i < DD; i += blockDim.x) w2[i] = Wf2[i];
    if (threadIdx.x < NTOK) ms[threadIdx.x] = masks[(b * NP + p) * NTOK + threadIdx.x];
    __syncthreads();

    const float* p1 = g_Y + ((long)b * NTOT + (long)p * NTOK) * 2 * DD + DD;
    const float* p2 = g_p2 + ((long)b * NTAB + tbl) * NTOK * DD;
    float bv = bf2[0];
    float acc = 0.f;
    for (int idx = threadIdx.x; idx < NTOK * DD; idx += blockDim.x) {
        int tok = idx / DD, d = idx % DD;
        float v = p1[(long)tok * 2 * DD + d] + p2[tok * DD + d];
        float s = ms[tok] * w2[d] * fmaxf(v, 0.f);
        if (d == 0) s += bv * ms[tok];
        acc += s;
    }
    red[threadIdx.x] = acc;
    __syncthreads();
    for (int s = 128; s > 0; s >>= 1) {
        if (threadIdx.x < s) red[threadIdx.x] += red[threadIdx.x + s];
        __syncthreads();
    }
    if (threadIdx.x == 0) out[b * NP + p] = red[0];
}

// ---------------- launcher --------------------------------------------------
extern "C" void kernel_launch(void* const* d_in, const int* in_sizes, int n_in,
                              void* d_out, int out_size)
{
    const float* ans   = (const float*)d_in[0];
    const float* qps   = (const float*)d_in[1];
    const float* masks = (const float*)d_in[2];
    const int*   tids  = (const int*)  d_in[3];
    const float* Wp    = (const float*)d_in[4];
    const float* bp    = (const float*)d_in[5];
    const float* Wt    = (const float*)d_in[6];
    const float* bt    = (const float*)d_in[7];
    const float* Wf1   = (const float*)d_in[8];
    const float* bf1   = (const float*)d_in[9];
    const float* Wf2   = (const float*)d_in[10];
    const float* bf2   = (const float*)d_in[11];
    float* out = (float*)d_out;

    void *pG, *pBias, *pY, *pTmax, *pP2;
    cudaGetSymbolAddress(&pG,    g_G);
    cudaGetSymbolAddress(&pBias, g_bias);
    cudaGetSymbolAddress(&pY,    g_Y);
    cudaGetSymbolAddress(&pTmax, g_tmax);
    cudaGetSymbolAddress(&pP2,   g_p2);

    // 1) G = Wf1_p @ [Wp_Q | Wp_AQ]
    gemm_k<<<dim3(1536 / 128, 768 / 128, 1), 256>>>(
        Wf1, 2 * DD, 0,
        Wp + DD, 1, 3 * DD, 0,
        (const float*)nullptr, 0,
        (float*)pG, 2 * DD, 0,
        DD, 2 * DD, DD);

    // 2) per-batch c_p, c_t ; 3) u
    prep1_k<<<dim3(3, BQ), 256>>>(ans, Wp, bp, Wt, bt);
    prep_u_k<<<dim3(3, BQ), 256>>>(Wf1, bf1);

    // 4) prepack Q and Wbig as SW128 fp16 tile images
    {
        long tq = (long)BQ * MT * 128 * 96;
        qsplit_k<<<(unsigned)((tq + 255) / 256), 256>>>(qps);
        long tw = (long)BQ * NT * 256 * 96;
        wsplit_k<<<(unsigned)((tw + 255) / 256), 256>>>(ans, Wt);
    }

    // 5) main GEMM via mma.sync (fp16), TMA-engine bulk-copy pipeline
    {
        int dyn = 4 * STG64;   // 192KB
        cudaFuncSetAttribute(tgemm_k, cudaFuncAttributeMaxDynamicSharedMemorySize, dyn);
        tgemm_k<<<dim3(NT, MT, BQ), 512, dyn>>>((const float*)pBias, (float*)pY);
    }

    // 6) table group-max
    tmax_k<<<BQ * NTOK, DD>>>(tids);

    // 7) part2 = tmax @ Wf1_a^T
    gemm_k<<<dim3(768 / 128, (NTAB * NTOK + 127) / 128, BQ), 256>>>(
        (const float*)pTmax, DD, (long)NTAB * NTOK * DD,
        Wf1 + DD, 2 * DD, 1, 0,
        (const float*)nullptr, 0,
        (float*)pP2, DD, (long)NTAB * NTOK * DD,
        NTAB * NTOK, DD, DD);

    // 8) final masked reduction
    final_k<<<BQ * NP, 256>>>(masks, tids, Wf2, bf2, out);
}